// round 5
// baseline (speedup 1.0000x reference)
#include <cuda_runtime.h>
#include <cuda_bf16.h>
#include <cstdint>

#define N_NODES 50000
#define N_EDGES 800000
#define D 128
#define R 4
#define NSEG (N_NODES * R)      // 200000
#define NLAYER 3
#define KTOT 640                // R*D + D
#define MPAD 50048              // 391 * 128
#define NTILES 391
#define NCHUNK 10               // K chunks of 64 bf16 (128B rows)

// ---------------- static device scratch ----------------
__device__ __align__(16) __nv_bfloat16 g_ah[(size_t)MPAD * KTOT];  // A hi  [node][640]
__device__ __align__(16) __nv_bfloat16 g_al[(size_t)MPAD * KTOT];  // A lo
__device__ __align__(16) __nv_bfloat16 g_bh[(size_t)NLAYER * D * KTOT]; // B hi [l][n][k]
__device__ __align__(16) __nv_bfloat16 g_bl[(size_t)NLAYER * D * KTOT]; // B lo
__device__ float g_x1[(size_t)N_NODES * D];
__device__ float g_x2[(size_t)N_NODES * D];
__device__ int   g_cnt[NSEG];
__device__ int   g_off[NSEG + 1];
__device__ int   g_cursor[NSEG];
__device__ int   g_bsum[256];
__device__ int   g_srcs[N_EDGES];

// ---------------- helpers ----------------
__device__ __forceinline__ uint32_t smem_to_u32(const void* p) {
    uint32_t a;
    asm("{ .reg .u64 t; cvta.to.shared.u64 t, %1; cvt.u32.u64 %0, t; }"
        : "=r"(a) : "l"(p));
    return a;
}

#define CP16(sm, gp) \
    asm volatile("cp.async.cg.shared.global [%0], [%1], 16;" :: "r"(sm), "l"(gp))

__device__ __forceinline__ void ldsm_x4(uint32_t* f, uint32_t addr) {
    asm volatile("ldmatrix.sync.aligned.m8n8.x4.shared.b16 {%0,%1,%2,%3}, [%4];"
                 : "=r"(f[0]), "=r"(f[1]), "=r"(f[2]), "=r"(f[3]) : "r"(addr));
}

__device__ __forceinline__ void mma16816(float* d, const uint32_t* a,
                                         uint32_t b0, uint32_t b1) {
    asm volatile(
        "mma.sync.aligned.m16n8k16.row.col.f32.bf16.bf16.f32 "
        "{%0,%1,%2,%3}, {%4,%5,%6,%7}, {%8,%9}, {%0,%1,%2,%3};"
        : "+f"(d[0]), "+f"(d[1]), "+f"(d[2]), "+f"(d[3])
        : "r"(a[0]), "r"(a[1]), "r"(a[2]), "r"(a[3]), "r"(b0), "r"(b1));
}

// ---------------- CSR build ----------------
__global__ void k_zero_cnt() {
    int i = blockIdx.x * blockDim.x + threadIdx.x;
    if (i < NSEG) g_cnt[i] = 0;
}

__global__ void k_hist(const int* __restrict__ dst, const int* __restrict__ et) {
    int e = blockIdx.x * blockDim.x + threadIdx.x;
    if (e < N_EDGES) atomicAdd(&g_cnt[dst[e] * R + et[e]], 1);
}

__global__ void k_scan1() {
    __shared__ int sh[1024];
    int t = threadIdx.x;
    int i = blockIdx.x * 1024 + t;
    int v = (i < NSEG) ? g_cnt[i] : 0;
    sh[t] = v;
    __syncthreads();
    for (int d = 1; d < 1024; d <<= 1) {
        int add = (t >= d) ? sh[t - d] : 0;
        __syncthreads();
        sh[t] += add;
        __syncthreads();
    }
    if (i < NSEG) g_off[i] = sh[t] - v;
    if (t == 1023) g_bsum[blockIdx.x] = sh[1023];
}

// fused scan2+scan3: every block redundantly scans the block sums
__global__ void k_scan23(int nb) {
    __shared__ int sh[256];
    int t = threadIdx.x;
    if (t < 256) sh[t] = (t < nb) ? g_bsum[t] : 0;
    __syncthreads();
    for (int d = 1; d < 256; d <<= 1) {
        int add = 0;
        if (t < 256 && t >= d) add = sh[t - d];
        __syncthreads();
        if (t < 256) sh[t] += add;
        __syncthreads();
    }
    int boff = (blockIdx.x > 0) ? sh[blockIdx.x - 1] : 0;
    int i = blockIdx.x * 1024 + t;
    if (i < NSEG) {
        int o = g_off[i] + boff;
        g_off[i] = o;
        g_cursor[i] = o;
    }
    if (i == 0) g_off[NSEG] = N_EDGES;
}

__global__ void k_scatter(const int* __restrict__ src, const int* __restrict__ dst,
                          const int* __restrict__ et) {
    int e = blockIdx.x * blockDim.x + threadIdx.x;
    if (e < N_EDGES) {
        int seg = dst[e] * R + et[e];
        int pos = atomicAdd(&g_cursor[seg], 1);
        g_srcs[pos] = src[e];
    }
}

// ---------------- weight prep: transpose + bf16 split ----------------
__global__ void k_bprep(const float* __restrict__ W, const float* __restrict__ root) {
    int i = blockIdx.x * 256 + threadIdx.x;     // over NLAYER*D*KTOT
    if (i >= NLAYER * D * KTOT) return;
    int k = i % KTOT;
    int t = i / KTOT;
    int n = t % D;
    int l = t / D;
    float w;
    if (k < 512) {
        int r = k >> 7, din = k & 127;
        w = W[(((size_t)l * R + r) * D + din) * D + n];
    } else {
        w = root[((size_t)l * D + (k - 512)) * D + n];
    }
    __nv_bfloat16 h = __float2bfloat16(w);
    float lo = w - __bfloat162float(h);
    g_bh[i] = h;
    g_bl[i] = __float2bfloat16(lo);
}

// ---------------- fill self-columns (512..639) of A from fp32 activations ----------------
__global__ void k_convx(const float* __restrict__ x) {
    int row = blockIdx.x * 8 + (threadIdx.x >> 5);
    if (row >= N_NODES) return;
    int lane = threadIdx.x & 31;
    float4 v = *reinterpret_cast<const float4*>(x + (size_t)row * D + lane * 4);
    __nv_bfloat16 h[4], lo[4];
    float vv[4] = {v.x, v.y, v.z, v.w};
#pragma unroll
    for (int j = 0; j < 4; j++) {
        h[j] = __float2bfloat16(vv[j]);
        lo[j] = __float2bfloat16(vv[j] - __bfloat162float(h[j]));
    }
    size_t o = (size_t)row * KTOT + 512 + lane * 4;
    *reinterpret_cast<uint2*>(&g_ah[o]) = *reinterpret_cast<uint2*>(h);
    *reinterpret_cast<uint2*>(&g_al[o]) = *reinterpret_cast<uint2*>(lo);
}

// ---------------- segment-mean aggregation (warp per segment) -> bf16 hi/lo ----------------
__global__ void k_agg(const float* __restrict__ x) {
    int seg = blockIdx.x * 8 + (threadIdx.x >> 5);
    if (seg >= NSEG) return;
    int lane = threadIdx.x & 31;
    int beg = g_off[seg];
    int end = g_off[seg + 1];
    float ax = 0.f, ay = 0.f, az = 0.f, aw = 0.f;
    for (int j = beg; j < end; j++) {
        int sn = g_srcs[j];
        float4 v = *reinterpret_cast<const float4*>(x + (size_t)sn * D + lane * 4);
        ax += v.x; ay += v.y; az += v.z; aw += v.w;
    }
    float inv = (end > beg) ? 1.0f / (float)(end - beg) : 0.0f;
    float vv[4] = {ax * inv, ay * inv, az * inv, aw * inv};
    __nv_bfloat16 h[4], lo[4];
#pragma unroll
    for (int j = 0; j < 4; j++) {
        h[j] = __float2bfloat16(vv[j]);
        lo[j] = __float2bfloat16(vv[j] - __bfloat162float(h[j]));
    }
    int node = seg >> 2;
    int r = seg & 3;
    size_t o = (size_t)node * KTOT + r * 128 + lane * 4;
    *reinterpret_cast<uint2*>(&g_ah[o]) = *reinterpret_cast<uint2*>(h);
    *reinterpret_cast<uint2*>(&g_al[o]) = *reinterpret_cast<uint2*>(lo);
}

// ---------------- HMMA GEMM + fused relu/residual/LayerNorm epilogue ----------------
// smem: [0:512) bias, tiles at 1024 + buf*65536: Ah(16K) Al(16K) Bh(16K) Bl(16K)
// epilogue reuses [1024, 1024+67584) as 128x132 f32 staging
#define SMEM_DYN (1024 + 2 * 65536)

__global__ void __launch_bounds__(256) k_gemm(int layer, const float* __restrict__ bias,
                                              const float* __restrict__ xin,
                                              const float* __restrict__ gamma,
                                              const float* __restrict__ beta,
                                              float* __restrict__ xout,
                                              int write_next) {
    extern __shared__ char smem[];
    float* sBias = (float*)smem;
    uint32_t smem_u = smem_to_u32(smem);
    int tid = threadIdx.x;
    int wid = tid >> 5;
    int lane = tid & 31;
    int brow = blockIdx.x * 128;

    if (tid < 32) {
        float4 b = *reinterpret_cast<const float4*>(bias + tid * 4);
        *reinterpret_cast<float4*>(&sBias[tid * 4]) = b;
    }

    const __nv_bfloat16* bh = g_bh + (size_t)layer * D * KTOT;
    const __nv_bfloat16* bl = g_bl + (size_t)layer * D * KTOT;

    // warp tile: 32 (m) x 64 (n)
    int wm = wid & 3;            // m0 = wm*32
    int wn = wid >> 2;           // n0 = wn*64
    int lrow = lane & 15;        // ldmatrix row within 16-row tile
    int kh16 = (lane >> 4) * 16; // k-half byte offset

    float acc[2][8][4];
#pragma unroll
    for (int t = 0; t < 2; t++)
#pragma unroll
        for (int q = 0; q < 8; q++)
#pragma unroll
            for (int j = 0; j < 4; j++) acc[t][q][j] = 0.f;

    auto load_chunk = [&](int c, int buf) {
        uint32_t base = smem_u + 1024 + buf * 65536;
        int kcol = c * 64;
#pragma unroll
        for (int it = 0; it < 4; it++) {
            int u = tid + it * 256;          // 0..1023
            int row = u >> 3;                // 0..127
            int c16 = u & 7;                 // 16B unit within 128B row
            uint32_t off = row * 128 + c16 * 16;
            uint32_t sw = off ^ ((off >> 3) & 0x70);
            const __nv_bfloat16* pa  = &g_ah[(size_t)(brow + row) * KTOT + kcol + c16 * 8];
            const __nv_bfloat16* pal = &g_al[(size_t)(brow + row) * KTOT + kcol + c16 * 8];
            const __nv_bfloat16* pb  = &bh[(size_t)row * KTOT + kcol + c16 * 8];
            const __nv_bfloat16* pbl = &bl[(size_t)row * KTOT + kcol + c16 * 8];
            CP16(base + sw, pa);
            CP16(base + 16384 + sw, pal);
            CP16(base + 32768 + sw, pb);
            CP16(base + 49152 + sw, pbl);
        }
        asm volatile("cp.async.commit_group;" ::: "memory");
    };

    load_chunk(0, 0);

    for (int c = 0; c < NCHUNK; c++) {
        if (c + 1 < NCHUNK) {
            load_chunk(c + 1, (c + 1) & 1);
            asm volatile("cp.async.wait_group 1;" ::: "memory");
        } else {
            asm volatile("cp.async.wait_group 0;" ::: "memory");
        }
        __syncthreads();

        uint32_t base = smem_u + 1024 + (c & 1) * 65536;
#pragma unroll
        for (int ks = 0; ks < 4; ks++) {
            int kb = ks * 32 + kh16;   // byte offset of k within chunk row
            uint32_t ah[2][4], al[2][4], bhf[4][4], blf[4][4];
#pragma unroll
            for (int t = 0; t < 2; t++) {
                int row = wm * 32 + t * 16 + lrow;
                uint32_t off = row * 128 + kb;
                ldsm_x4(ah[t], base + (off ^ ((off >> 3) & 0x70)));
            }
#pragma unroll
            for (int p = 0; p < 4; p++) {
                int row = wn * 64 + p * 16 + lrow;
                uint32_t off = row * 128 + kb;
                ldsm_x4(bhf[p], base + 32768 + (off ^ ((off >> 3) & 0x70)));
            }
            // pass 0: Ah * Bh
#pragma unroll
            for (int t = 0; t < 2; t++)
#pragma unroll
                for (int p = 0; p < 4; p++) {
                    mma16816(acc[t][2 * p + 0], ah[t], bhf[p][0], bhf[p][2]);
                    mma16816(acc[t][2 * p + 1], ah[t], bhf[p][1], bhf[p][3]);
                }
            // pass 1: Al * Bh
#pragma unroll
            for (int t = 0; t < 2; t++) {
                int row = wm * 32 + t * 16 + lrow;
                uint32_t off = row * 128 + kb;
                ldsm_x4(al[t], base + 16384 + (off ^ ((off >> 3) & 0x70)));
            }
#pragma unroll
            for (int t = 0; t < 2; t++)
#pragma unroll
                for (int p = 0; p < 4; p++) {
                    mma16816(acc[t][2 * p + 0], al[t], bhf[p][0], bhf[p][2]);
                    mma16816(acc[t][2 * p + 1], al[t], bhf[p][1], bhf[p][3]);
                }
            // pass 2: Ah * Bl
#pragma unroll
            for (int p = 0; p < 4; p++) {
                int row = wn * 64 + p * 16 + lrow;
                uint32_t off = row * 128 + kb;
                ldsm_x4(blf[p], base + 49152 + (off ^ ((off >> 3) & 0x70)));
            }
#pragma unroll
            for (int t = 0; t < 2; t++)
#pragma unroll
                for (int p = 0; p < 4; p++) {
                    mma16816(acc[t][2 * p + 0], ah[t], blf[p][0], blf[p][2]);
                    mma16816(acc[t][2 * p + 1], ah[t], blf[p][1], blf[p][3]);
                }
        }
        __syncthreads();
    }

    // ---- stage acc + bias into smem (reuse tile area), stride 132 floats ----
    float* sOut = (float*)(smem + 1024);
#pragma unroll
    for (int t = 0; t < 2; t++) {
        int rr = wm * 32 + t * 16 + (lane >> 2);
#pragma unroll
        for (int q = 0; q < 8; q++) {
            int col = wn * 64 + (q >> 1) * 16 + (q & 1) * 8 + 2 * (lane & 3);
            float bx = sBias[col], by = sBias[col + 1];
            *reinterpret_cast<float2*>(&sOut[rr * 132 + col]) =
                make_float2(acc[t][q][0] + bx, acc[t][q][1] + by);
            *reinterpret_cast<float2*>(&sOut[(rr + 8) * 132 + col]) =
                make_float2(acc[t][q][2] + bx, acc[t][q][3] + by);
        }
    }
    __syncthreads();

    // ---- fused relu + residual + LayerNorm (+ next-layer bf16 self-cols) ----
    for (int rr = wid; rr < 128; rr += 8) {
        int row = brow + rr;
        if (row >= N_NODES) continue;
        float4 t = *reinterpret_cast<float4*>(&sOut[rr * 132 + lane * 4]);
        float4 xr = *reinterpret_cast<const float4*>(xin + (size_t)row * D + lane * 4);
        float4 v;
        v.x = fmaxf(t.x, 0.f) + xr.x;
        v.y = fmaxf(t.y, 0.f) + xr.y;
        v.z = fmaxf(t.z, 0.f) + xr.z;
        v.w = fmaxf(t.w, 0.f) + xr.w;
        float s = v.x + v.y + v.z + v.w;
        float sq = v.x * v.x + v.y * v.y + v.z * v.z + v.w * v.w;
#pragma unroll
        for (int o = 16; o; o >>= 1) {
            s += __shfl_xor_sync(0xFFFFFFFFu, s, o);
            sq += __shfl_xor_sync(0xFFFFFFFFu, sq, o);
        }
        float mean = s * (1.0f / 128.0f);
        float var = sq * (1.0f / 128.0f) - mean * mean;
        float rs = rsqrtf(var + 1e-5f);
        float4 g = *reinterpret_cast<const float4*>(gamma + lane * 4);
        float4 b = *reinterpret_cast<const float4*>(beta + lane * 4);
        float4 o;
        o.x = (v.x - mean) * rs * g.x + b.x;
        o.y = (v.y - mean) * rs * g.y + b.y;
        o.z = (v.z - mean) * rs * g.z + b.z;
        o.w = (v.w - mean) * rs * g.w + b.w;
        *reinterpret_cast<float4*>(xout + (size_t)row * D + lane * 4) = o;
        if (write_next) {
            float vv[4] = {o.x, o.y, o.z, o.w};
            __nv_bfloat16 h[4], lo[4];
#pragma unroll
            for (int j = 0; j < 4; j++) {
                h[j] = __float2bfloat16(vv[j]);
                lo[j] = __float2bfloat16(vv[j] - __bfloat162float(h[j]));
            }
            size_t oo = (size_t)row * KTOT + 512 + lane * 4;
            *reinterpret_cast<uint2*>(&g_ah[oo]) = *reinterpret_cast<uint2*>(h);
            *reinterpret_cast<uint2*>(&g_al[oo]) = *reinterpret_cast<uint2*>(lo);
        }
    }
}

// ---------------- host launcher ----------------
extern "C" void kernel_launch(void* const* d_in, const int* in_sizes, int n_in,
                              void* d_out, int out_size) {
    const float* x     = (const float*)d_in[0];
    const int*   ei    = (const int*)d_in[1];
    const int*   et    = (const int*)d_in[2];
    const float* W     = (const float*)d_in[3];
    const float* root  = (const float*)d_in[4];
    const float* bias  = (const float*)d_in[5];
    const float* gamma = (const float*)d_in[6];
    const float* beta  = (const float*)d_in[7];
    float* out = (float*)d_out;

    const int* src = ei;
    const int* dst = ei + N_EDGES;

    float *px1 = nullptr, *px2 = nullptr;
    cudaGetSymbolAddress((void**)&px1, g_x1);
    cudaGetSymbolAddress((void**)&px2, g_x2);

    cudaFuncSetAttribute(k_gemm, cudaFuncAttributeMaxDynamicSharedMemorySize, SMEM_DYN);

    // CSR build (edge structure is layer-invariant)
    k_zero_cnt<<<(NSEG + 255) / 256, 256>>>();
    k_hist<<<(N_EDGES + 255) / 256, 256>>>(dst, et);
    int nb = (NSEG + 1023) / 1024;
    k_scan1<<<nb, 1024>>>();
    k_scan23<<<nb, 1024>>>(nb);
    k_scatter<<<(N_EDGES + 255) / 256, 256>>>(src, dst, et);

    // weight transpose + split
    k_bprep<<<(NLAYER * D * KTOT + 255) / 256, 256>>>(W, root);
    // self-cols for layer 0
    k_convx<<<(N_NODES + 7) / 8, 256>>>(x);

    const float* xin = x;
    for (int l = 0; l < NLAYER; l++) {
        k_agg<<<(NSEG + 7) / 8, 256>>>(xin);
        float* xout = (l == NLAYER - 1) ? out : ((l == 0) ? px1 : px2);
        k_gemm<<<NTILES, 256, SMEM_DYN>>>(l, bias + (size_t)l * D, xin,
                                          gamma + (size_t)l * D,
                                          beta + (size_t)l * D, xout,
                                          l < NLAYER - 1 ? 1 : 0);
        xin = xout;
    }
}

// round 7
// speedup vs baseline: 1.1180x; 1.1180x over previous
#include <cuda_runtime.h>
#include <cuda_bf16.h>
#include <cstdint>

#define N_NODES 50000
#define N_EDGES 800000
#define D 128
#define R 4
#define NSEG (N_NODES * R)      // 200000
#define NLAYER 3
#define KTOT 640                // R*D + D
#define MPAD 50048              // 391 * 128
#define NTILES 391
#define NCHUNK 10               // K chunks of 64 bf16 (128B rows)

// ---------------- static device scratch ----------------
__device__ __align__(16) __nv_bfloat16 g_ah[(size_t)MPAD * KTOT];  // A hi  [node][640]
__device__ __align__(16) __nv_bfloat16 g_al[(size_t)MPAD * KTOT];  // A lo
__device__ __align__(16) __nv_bfloat16 g_bh[(size_t)NLAYER * D * KTOT]; // B hi [l][n][k]
__device__ __align__(16) __nv_bfloat16 g_bl[(size_t)NLAYER * D * KTOT]; // B lo
__device__ float g_tmp[(size_t)N_NODES * D];     // GEMM output before epilogue
__device__ float g_x1[(size_t)N_NODES * D];
__device__ float g_x2[(size_t)N_NODES * D];
__device__ int   g_cnt[NSEG];
__device__ int   g_off[NSEG + 1];
__device__ int   g_cursor[NSEG];
__device__ int   g_bsum[256];
__device__ int   g_srcs[N_EDGES];

// ---------------- helpers ----------------
__device__ __forceinline__ uint32_t smem_to_u32(const void* p) {
    uint32_t a;
    asm("{ .reg .u64 t; cvta.to.shared.u64 t, %1; cvt.u32.u64 %0, t; }"
        : "=r"(a) : "l"(p));
    return a;
}

#define CP16(sm, gp) \
    asm volatile("cp.async.cg.shared.global [%0], [%1], 16;" :: "r"(sm), "l"(gp))

__device__ __forceinline__ void ldsm_x4(uint32_t* f, uint32_t addr) {
    asm volatile("ldmatrix.sync.aligned.m8n8.x4.shared.b16 {%0,%1,%2,%3}, [%4];"
                 : "=r"(f[0]), "=r"(f[1]), "=r"(f[2]), "=r"(f[3]) : "r"(addr));
}

__device__ __forceinline__ void mma16816(float* d, const uint32_t* a,
                                         uint32_t b0, uint32_t b1) {
    asm volatile(
        "mma.sync.aligned.m16n8k16.row.col.f32.bf16.bf16.f32 "
        "{%0,%1,%2,%3}, {%4,%5,%6,%7}, {%8,%9}, {%0,%1,%2,%3};"
        : "+f"(d[0]), "+f"(d[1]), "+f"(d[2]), "+f"(d[3])
        : "r"(a[0]), "r"(a[1]), "r"(a[2]), "r"(a[3]), "r"(b0), "r"(b1));
}

// ---------------- CSR build ----------------
__global__ void k_zero_cnt() {
    int i = blockIdx.x * blockDim.x + threadIdx.x;
    if (i < NSEG) g_cnt[i] = 0;
}

__global__ void k_hist(const int* __restrict__ dst, const int* __restrict__ et) {
    int e = blockIdx.x * blockDim.x + threadIdx.x;
    if (e < N_EDGES) atomicAdd(&g_cnt[dst[e] * R + et[e]], 1);
}

__global__ void k_scan1() {
    __shared__ int sh[1024];
    int t = threadIdx.x;
    int i = blockIdx.x * 1024 + t;
    int v = (i < NSEG) ? g_cnt[i] : 0;
    sh[t] = v;
    __syncthreads();
    for (int d = 1; d < 1024; d <<= 1) {
        int add = (t >= d) ? sh[t - d] : 0;
        __syncthreads();
        sh[t] += add;
        __syncthreads();
    }
    if (i < NSEG) g_off[i] = sh[t] - v;
    if (t == 1023) g_bsum[blockIdx.x] = sh[1023];
}

// fused scan2+scan3: every block redundantly scans the block sums
__global__ void k_scan23(int nb) {
    __shared__ int sh[256];
    int t = threadIdx.x;
    if (t < 256) sh[t] = (t < nb) ? g_bsum[t] : 0;
    __syncthreads();
    for (int d = 1; d < 256; d <<= 1) {
        int add = 0;
        if (t < 256 && t >= d) add = sh[t - d];
        __syncthreads();
        if (t < 256) sh[t] += add;
        __syncthreads();
    }
    int boff = (blockIdx.x > 0) ? sh[blockIdx.x - 1] : 0;
    int i = blockIdx.x * 1024 + t;
    if (i < NSEG) {
        int o = g_off[i] + boff;
        g_off[i] = o;
        g_cursor[i] = o;
    }
    if (i == 0) g_off[NSEG] = N_EDGES;
}

__global__ void k_scatter(const int* __restrict__ src, const int* __restrict__ dst,
                          const int* __restrict__ et) {
    int e = blockIdx.x * blockDim.x + threadIdx.x;
    if (e < N_EDGES) {
        int seg = dst[e] * R + et[e];
        int pos = atomicAdd(&g_cursor[seg], 1);
        g_srcs[pos] = src[e];
    }
}

// ---------------- weight prep: transpose + bf16 split ----------------
__global__ void k_bprep(const float* __restrict__ W, const float* __restrict__ root) {
    int i = blockIdx.x * 256 + threadIdx.x;     // over NLAYER*D*KTOT
    if (i >= NLAYER * D * KTOT) return;
    int k = i % KTOT;
    int t = i / KTOT;
    int n = t % D;
    int l = t / D;
    float w;
    if (k < 512) {
        int r = k >> 7, din = k & 127;
        w = W[(((size_t)l * R + r) * D + din) * D + n];
    } else {
        w = root[((size_t)l * D + (k - 512)) * D + n];
    }
    __nv_bfloat16 h = __float2bfloat16(w);
    float lo = w - __bfloat162float(h);
    g_bh[i] = h;
    g_bl[i] = __float2bfloat16(lo);
}

// ---------------- fill self-columns (512..639) of A from fp32 activations ----------------
__global__ void k_convx(const float* __restrict__ x) {
    int row = blockIdx.x * 8 + (threadIdx.x >> 5);
    if (row >= N_NODES) return;
    int lane = threadIdx.x & 31;
    float4 v = *reinterpret_cast<const float4*>(x + (size_t)row * D + lane * 4);
    __nv_bfloat16 h[4], lo[4];
    float vv[4] = {v.x, v.y, v.z, v.w};
#pragma unroll
    for (int j = 0; j < 4; j++) {
        h[j] = __float2bfloat16(vv[j]);
        lo[j] = __float2bfloat16(vv[j] - __bfloat162float(h[j]));
    }
    size_t o = (size_t)row * KTOT + 512 + lane * 4;
    *reinterpret_cast<uint2*>(&g_ah[o]) = *reinterpret_cast<uint2*>(h);
    *reinterpret_cast<uint2*>(&g_al[o]) = *reinterpret_cast<uint2*>(lo);
}

// ---------------- segment-mean aggregation (warp per segment) -> bf16 hi/lo ----------------
__global__ void k_agg(const float* __restrict__ x) {
    int seg = blockIdx.x * 8 + (threadIdx.x >> 5);
    if (seg >= NSEG) return;
    int lane = threadIdx.x & 31;
    int beg = g_off[seg];
    int end = g_off[seg + 1];
    float ax = 0.f, ay = 0.f, az = 0.f, aw = 0.f;
    for (int j = beg; j < end; j++) {
        int sn = g_srcs[j];
        float4 v = *reinterpret_cast<const float4*>(x + (size_t)sn * D + lane * 4);
        ax += v.x; ay += v.y; az += v.z; aw += v.w;
    }
    float inv = (end > beg) ? 1.0f / (float)(end - beg) : 0.0f;
    float vv[4] = {ax * inv, ay * inv, az * inv, aw * inv};
    __nv_bfloat16 h[4], lo[4];
#pragma unroll
    for (int j = 0; j < 4; j++) {
        h[j] = __float2bfloat16(vv[j]);
        lo[j] = __float2bfloat16(vv[j] - __bfloat162float(h[j]));
    }
    int node = seg >> 2;
    int r = seg & 3;
    size_t o = (size_t)node * KTOT + r * 128 + lane * 4;
    *reinterpret_cast<uint2*>(&g_ah[o]) = *reinterpret_cast<uint2*>(h);
    *reinterpret_cast<uint2*>(&g_al[o]) = *reinterpret_cast<uint2*>(lo);
}

// ---------------- HMMA GEMM, occupancy-2 variant ----------------
// smem: [0:512) bias
//       A tiles (double buffered): 1024 + buf*32768 : {Ah 16K, Al 16K}
//       B tile (single buffered):  1024 + 65536     : {Bh 16K, Bl 16K}
#define SMEM_DYN (1024 + 2 * 32768 + 32768)   // 99328 -> 2 CTAs/SM

__global__ void __launch_bounds__(256, 2) k_gemm(int layer, const float* __restrict__ bias) {
    extern __shared__ char smem[];
    float* sBias = (float*)smem;
    uint32_t smem_u = smem_to_u32(smem);
    int tid = threadIdx.x;
    int wid = tid >> 5;
    int lane = tid & 31;
    int brow = blockIdx.x * 128;

    if (tid < 32) {
        float4 b = *reinterpret_cast<const float4*>(bias + tid * 4);
        *reinterpret_cast<float4*>(&sBias[tid * 4]) = b;
    }

    const __nv_bfloat16* bh = g_bh + (size_t)layer * D * KTOT;
    const __nv_bfloat16* bl = g_bl + (size_t)layer * D * KTOT;

    // warp tile: 32 (m) x 64 (n)
    int wm = wid & 3;            // m0 = wm*32
    int wn = wid >> 2;           // n0 = wn*64
    int lrow = lane & 15;
    int kh16 = (lane >> 4) * 16;

    const uint32_t bBase = smem_u + 1024 + 65536;

    float acc[2][8][4];
#pragma unroll
    for (int t = 0; t < 2; t++)
#pragma unroll
        for (int q = 0; q < 8; q++)
#pragma unroll
            for (int j = 0; j < 4; j++) acc[t][q][j] = 0.f;

    auto load_A = [&](int c, int buf) {
        uint32_t base = smem_u + 1024 + buf * 32768;
        int kcol = c * 64;
#pragma unroll
        for (int it = 0; it < 4; it++) {
            int u = tid + it * 256;          // 0..1023
            int row = u >> 3;                // 0..127
            int c16 = u & 7;
            uint32_t off = row * 128 + c16 * 16;
            uint32_t sw = off ^ ((off >> 3) & 0x70);
            CP16(base + sw,         &g_ah[(size_t)(brow + row) * KTOT + kcol + c16 * 8]);
            CP16(base + 16384 + sw, &g_al[(size_t)(brow + row) * KTOT + kcol + c16 * 8]);
        }
        asm volatile("cp.async.commit_group;" ::: "memory");
    };
    auto load_B = [&](int c) {
        int kcol = c * 64;
#pragma unroll
        for (int it = 0; it < 4; it++) {
            int u = tid + it * 256;
            int row = u >> 3;
            int c16 = u & 7;
            uint32_t off = row * 128 + c16 * 16;
            uint32_t sw = off ^ ((off >> 3) & 0x70);
            CP16(bBase + sw,         &bh[(size_t)row * KTOT + kcol + c16 * 8]);
            CP16(bBase + 16384 + sw, &bl[(size_t)row * KTOT + kcol + c16 * 8]);
        }
        asm volatile("cp.async.commit_group;" ::: "memory");
    };

    load_A(0, 0);
    load_B(0);

    for (int c = 0; c < NCHUNK; c++) {
        asm volatile("cp.async.wait_group 0;" ::: "memory");
        __syncthreads();
        if (c + 1 < NCHUNK) load_A(c + 1, (c + 1) & 1);   // A buffer (c+1)&1 is free

        uint32_t base = smem_u + 1024 + (c & 1) * 32768;
#pragma unroll
        for (int ks = 0; ks < 4; ks++) {
            int kb = ks * 32 + kh16;
            uint32_t ah[2][4], al[2][4], bhf[4][4], blf[4][4];
#pragma unroll
            for (int t = 0; t < 2; t++) {
                int row = wm * 32 + t * 16 + lrow;
                uint32_t off = row * 128 + kb;
                ldsm_x4(ah[t], base + (off ^ ((off >> 3) & 0x70)));
            }
#pragma unroll
            for (int p = 0; p < 4; p++) {
                int row = wn * 64 + p * 16 + lrow;
                uint32_t off = row * 128 + kb;
                ldsm_x4(bhf[p], bBase + (off ^ ((off >> 3) & 0x70)));
            }
            // pass 0: Ah * Bh
#pragma unroll
            for (int t = 0; t < 2; t++)
#pragma unroll
                for (int p = 0; p < 4; p++) {
                    mma16816(acc[t][2 * p + 0], ah[t], bhf[p][0], bhf[p][2]);
                    mma16816(acc[t][2 * p + 1], ah[t], bhf[p][1], bhf[p][3]);
                }
            // pass 1: Al * Bh
#pragma unroll
            for (int t = 0; t < 2; t++) {
                int row = wm * 32 + t * 16 + lrow;
                uint32_t off = row * 128 + kb;
                ldsm_x4(al[t], base + 16384 + (off ^ ((off >> 3) & 0x70)));
            }
#pragma unroll
            for (int t = 0; t < 2; t++)
#pragma unroll
                for (int p = 0; p < 4; p++) {
                    mma16816(acc[t][2 * p + 0], al[t], bhf[p][0], bhf[p][2]);
                    mma16816(acc[t][2 * p + 1], al[t], bhf[p][1], bhf[p][3]);
                }
            // pass 2: Ah * Bl
#pragma unroll
            for (int p = 0; p < 4; p++) {
                int row = wn * 64 + p * 16 + lrow;
                uint32_t off = row * 128 + kb;
                ldsm_x4(blf[p], bBase + 16384 + (off ^ ((off >> 3) & 0x70)));
            }
#pragma unroll
            for (int t = 0; t < 2; t++)
#pragma unroll
                for (int p = 0; p < 4; p++) {
                    mma16816(acc[t][2 * p + 0], ah[t], blf[p][0], blf[p][2]);
                    mma16816(acc[t][2 * p + 1], ah[t], blf[p][1], blf[p][3]);
                }
        }
        __syncthreads();                         // all warps done with B(c)
        if (c + 1 < NCHUNK) load_B(c + 1);       // refill single B buffer
    }

    // ---- epilogue: + bias, write to g_tmp ----
#pragma unroll
    for (int t = 0; t < 2; t++) {
        int mrow = brow + wm * 32 + t * 16 + (lane >> 2);
#pragma unroll
        for (int q = 0; q < 8; q++) {
            int col = wn * 64 + (q >> 1) * 16 + (q & 1) * 8 + 2 * (lane & 3);
            float bx = sBias[col], by = sBias[col + 1];
            if (mrow < N_NODES) {
                float2 o0 = make_float2(acc[t][q][0] + bx, acc[t][q][1] + by);
                *reinterpret_cast<float2*>(g_tmp + (size_t)mrow * D + col) = o0;
            }
            if (mrow + 8 < N_NODES) {
                float2 o1 = make_float2(acc[t][q][2] + bx, acc[t][q][3] + by);
                *reinterpret_cast<float2*>(g_tmp + (size_t)(mrow + 8) * D + col) = o1;
            }
        }
    }
}

// ---------------- epilogue: relu + residual + layernorm (+ bf16 self-cols) ----------------
__global__ void k_epi(const float* __restrict__ xin, const float* __restrict__ gamma,
                      const float* __restrict__ beta, float* __restrict__ xout,
                      int write_next) {
    int row = blockIdx.x * 8 + (threadIdx.x >> 5);
    if (row >= N_NODES) return;
    int lane = threadIdx.x & 31;
    float4 t = *reinterpret_cast<const float4*>(g_tmp + (size_t)row * D + lane * 4);
    float4 xr = *reinterpret_cast<const float4*>(xin + (size_t)row * D + lane * 4);
    float4 v;
    v.x = fmaxf(t.x, 0.f) + xr.x;
    v.y = fmaxf(t.y, 0.f) + xr.y;
    v.z = fmaxf(t.z, 0.f) + xr.z;
    v.w = fmaxf(t.w, 0.f) + xr.w;
    float s = v.x + v.y + v.z + v.w;
    float sq = v.x * v.x + v.y * v.y + v.z * v.z + v.w * v.w;
#pragma unroll
    for (int o = 16; o; o >>= 1) {
        s += __shfl_xor_sync(0xFFFFFFFFu, s, o);
        sq += __shfl_xor_sync(0xFFFFFFFFu, sq, o);
    }
    float mean = s * (1.0f / 128.0f);
    float var = sq * (1.0f / 128.0f) - mean * mean;
    float rs = rsqrtf(var + 1e-5f);
    float4 g = *reinterpret_cast<const float4*>(gamma + lane * 4);
    float4 b = *reinterpret_cast<const float4*>(beta + lane * 4);
    float4 o;
    o.x = (v.x - mean) * rs * g.x + b.x;
    o.y = (v.y - mean) * rs * g.y + b.y;
    o.z = (v.z - mean) * rs * g.z + b.z;
    o.w = (v.w - mean) * rs * g.w + b.w;
    *reinterpret_cast<float4*>(xout + (size_t)row * D + lane * 4) = o;
    if (write_next) {
        float vv[4] = {o.x, o.y, o.z, o.w};
        __nv_bfloat16 h[4], lo[4];
#pragma unroll
        for (int j = 0; j < 4; j++) {
            h[j] = __float2bfloat16(vv[j]);
            lo[j] = __float2bfloat16(vv[j] - __bfloat162float(h[j]));
        }
        size_t oo = (size_t)row * KTOT + 512 + lane * 4;
        *reinterpret_cast<uint2*>(&g_ah[oo]) = *reinterpret_cast<uint2*>(h);
        *reinterpret_cast<uint2*>(&g_al[oo]) = *reinterpret_cast<uint2*>(lo);
    }
}

// ---------------- host launcher ----------------
extern "C" void kernel_launch(void* const* d_in, const int* in_sizes, int n_in,
                              void* d_out, int out_size) {
    const float* x     = (const float*)d_in[0];
    const int*   ei    = (const int*)d_in[1];
    const int*   et    = (const int*)d_in[2];
    const float* W     = (const float*)d_in[3];
    const float* root  = (const float*)d_in[4];
    const float* bias  = (const float*)d_in[5];
    const float* gamma = (const float*)d_in[6];
    const float* beta  = (const float*)d_in[7];
    float* out = (float*)d_out;

    const int* src = ei;
    const int* dst = ei + N_EDGES;

    float *px1 = nullptr, *px2 = nullptr;
    cudaGetSymbolAddress((void**)&px1, g_x1);
    cudaGetSymbolAddress((void**)&px2, g_x2);

    cudaFuncSetAttribute(k_gemm, cudaFuncAttributeMaxDynamicSharedMemorySize, SMEM_DYN);

    // CSR build (edge structure is layer-invariant)
    k_zero_cnt<<<(NSEG + 255) / 256, 256>>>();
    k_hist<<<(N_EDGES + 255) / 256, 256>>>(dst, et);
    int nb = (NSEG + 1023) / 1024;
    k_scan1<<<nb, 1024>>>();
    k_scan23<<<nb, 1024>>>(nb);
    k_scatter<<<(N_EDGES + 255) / 256, 256>>>(src, dst, et);

    // weight transpose + split
    k_bprep<<<(NLAYER * D * KTOT + 255) / 256, 256>>>(W, root);
    // self-cols for layer 0
    k_convx<<<(N_NODES + 7) / 8, 256>>>(x);

    const float* xin = x;
    for (int l = 0; l < NLAYER; l++) {
        k_agg<<<(NSEG + 7) / 8, 256>>>(xin);
        k_gemm<<<NTILES, 256, SMEM_DYN>>>(l, bias + (size_t)l * D);
        float* xout = (l == NLAYER - 1) ? out : ((l == 0) ? px1 : px2);
        k_epi<<<(N_NODES + 7) / 8, 256>>>(xin, gamma + (size_t)l * D,
                                          beta + (size_t)l * D, xout,
                                          l < NLAYER - 1 ? 1 : 0);
        xin = xout;
    }
}

// round 9
// speedup vs baseline: 1.2911x; 1.1549x over previous
#include <cuda_runtime.h>
#include <cuda_fp16.h>
#include <cstdint>

#define N_NODES 50000
#define N_EDGES 800000
#define D 128
#define R 4
#define NSEG (N_NODES * R)      // 200000
#define NLAYER 3
#define KTOT 640                // R*D + D
#define MPAD 50048              // 391 * 128
#define NTILES 391
#define NCHUNK 10               // K chunks of 64 fp16 (128B rows)

// ---------------- static device scratch ----------------
__device__ __align__(16) __half g_ah[(size_t)MPAD * KTOT];        // A hi  [node][640]
__device__ __align__(16) __half g_al[(size_t)MPAD * KTOT];        // A lo
__device__ __align__(16) __half g_bh[(size_t)NLAYER * D * KTOT];  // B hi [l][n][k]
__device__ float g_tmp[(size_t)N_NODES * D];     // GEMM output before epilogue
__device__ float g_x1[(size_t)N_NODES * D];
__device__ float g_x2[(size_t)N_NODES * D];
__device__ int   g_cnt[NSEG];
__device__ int   g_off[NSEG + 1];
__device__ int   g_cursor[NSEG];
__device__ int   g_bsum[256];
__device__ int   g_srcs[N_EDGES];

// ---------------- helpers ----------------
__device__ __forceinline__ uint32_t smem_to_u32(const void* p) {
    uint32_t a;
    asm("{ .reg .u64 t; cvta.to.shared.u64 t, %1; cvt.u32.u64 %0, t; }"
        : "=r"(a) : "l"(p));
    return a;
}

#define CP16(sm, gp) \
    asm volatile("cp.async.cg.shared.global [%0], [%1], 16;" :: "r"(sm), "l"(gp))

__device__ __forceinline__ void ldsm_x4(uint32_t* f, uint32_t addr) {
    asm volatile("ldmatrix.sync.aligned.m8n8.x4.shared.b16 {%0,%1,%2,%3}, [%4];"
                 : "=r"(f[0]), "=r"(f[1]), "=r"(f[2]), "=r"(f[3]) : "r"(addr));
}

__device__ __forceinline__ void mma16816(float* d, const uint32_t* a,
                                         uint32_t b0, uint32_t b1) {
    asm volatile(
        "mma.sync.aligned.m16n8k16.row.col.f32.f16.f16.f32 "
        "{%0,%1,%2,%3}, {%4,%5,%6,%7}, {%8,%9}, {%0,%1,%2,%3};"
        : "+f"(d[0]), "+f"(d[1]), "+f"(d[2]), "+f"(d[3])
        : "r"(a[0]), "r"(a[1]), "r"(a[2]), "r"(a[3]), "r"(b0), "r"(b1));
}

// ---------------- CSR build ----------------
__global__ void k_zero_cnt() {
    int i = blockIdx.x * blockDim.x + threadIdx.x;
    if (i < NSEG) g_cnt[i] = 0;
}

__global__ void k_hist(const int* __restrict__ dst, const int* __restrict__ et) {
    int e = blockIdx.x * blockDim.x + threadIdx.x;
    if (e < N_EDGES) atomicAdd(&g_cnt[dst[e] * R + et[e]], 1);
}

__global__ void k_scan1() {
    __shared__ int sh[1024];
    int t = threadIdx.x;
    int i = blockIdx.x * 1024 + t;
    int v = (i < NSEG) ? g_cnt[i] : 0;
    sh[t] = v;
    __syncthreads();
    for (int d = 1; d < 1024; d <<= 1) {
        int add = (t >= d) ? sh[t - d] : 0;
        __syncthreads();
        sh[t] += add;
        __syncthreads();
    }
    if (i < NSEG) g_off[i] = sh[t] - v;
    if (t == 1023) g_bsum[blockIdx.x] = sh[1023];
}

// fused scan2+scan3: every block redundantly scans the block sums
__global__ void k_scan23(int nb) {
    __shared__ int sh[256];
    int t = threadIdx.x;
    if (t < 256) sh[t] = (t < nb) ? g_bsum[t] : 0;
    __syncthreads();
    for (int d = 1; d < 256; d <<= 1) {
        int add = 0;
        if (t < 256 && t >= d) add = sh[t - d];
        __syncthreads();
        if (t < 256) sh[t] += add;
        __syncthreads();
    }
    int boff = (blockIdx.x > 0) ? sh[blockIdx.x - 1] : 0;
    int i = blockIdx.x * 1024 + t;
    if (i < NSEG) {
        int o = g_off[i] + boff;
        g_off[i] = o;
        g_cursor[i] = o;
    }
    if (i == 0) g_off[NSEG] = N_EDGES;
}

__global__ void k_scatter(const int* __restrict__ src, const int* __restrict__ dst,
                          const int* __restrict__ et) {
    int e = blockIdx.x * blockDim.x + threadIdx.x;
    if (e < N_EDGES) {
        int seg = dst[e] * R + et[e];
        int pos = atomicAdd(&g_cursor[seg], 1);
        g_srcs[pos] = src[e];
    }
}

// ---------------- weight prep: transpose + fp16 (hi only; A carries the split) ----------------
__global__ void k_bprep(const float* __restrict__ W, const float* __restrict__ root) {
    int i = blockIdx.x * 256 + threadIdx.x;     // over NLAYER*D*KTOT
    if (i >= NLAYER * D * KTOT) return;
    int k = i % KTOT;
    int t = i / KTOT;
    int n = t % D;
    int l = t / D;
    float w;
    if (k < 512) {
        int r = k >> 7, din = k & 127;
        w = W[(((size_t)l * R + r) * D + din) * D + n];
    } else {
        w = root[((size_t)l * D + (k - 512)) * D + n];
    }
    g_bh[i] = __float2half_rn(w);
}

// ---------------- fill self-columns (512..639) of A from fp32 activations ----------------
__global__ void k_convx(const float* __restrict__ x) {
    int row = blockIdx.x * 8 + (threadIdx.x >> 5);
    if (row >= N_NODES) return;
    int lane = threadIdx.x & 31;
    float4 v = *reinterpret_cast<const float4*>(x + (size_t)row * D + lane * 4);
    __half h[4], lo[4];
    float vv[4] = {v.x, v.y, v.z, v.w};
#pragma unroll
    for (int j = 0; j < 4; j++) {
        h[j] = __float2half_rn(vv[j]);
        lo[j] = __float2half_rn(vv[j] - __half2float(h[j]));
    }
    size_t o = (size_t)row * KTOT + 512 + lane * 4;
    *reinterpret_cast<uint2*>(&g_ah[o]) = *reinterpret_cast<uint2*>(h);
    *reinterpret_cast<uint2*>(&g_al[o]) = *reinterpret_cast<uint2*>(lo);
}

// ---------------- segment-mean aggregation (warp per segment) -> fp16 hi/lo ----------------
__global__ void k_agg(const float* __restrict__ x) {
    int seg = blockIdx.x * 8 + (threadIdx.x >> 5);
    if (seg >= NSEG) return;
    int lane = threadIdx.x & 31;
    int beg = g_off[seg];
    int end = g_off[seg + 1];
    float ax = 0.f, ay = 0.f, az = 0.f, aw = 0.f;
    for (int j = beg; j < end; j++) {
        int sn = g_srcs[j];
        float4 v = *reinterpret_cast<const float4*>(x + (size_t)sn * D + lane * 4);
        ax += v.x; ay += v.y; az += v.z; aw += v.w;
    }
    float inv = (end > beg) ? 1.0f / (float)(end - beg) : 0.0f;
    float vv[4] = {ax * inv, ay * inv, az * inv, aw * inv};
    __half h[4], lo[4];
#pragma unroll
    for (int j = 0; j < 4; j++) {
        h[j] = __float2half_rn(vv[j]);
        lo[j] = __float2half_rn(vv[j] - __half2float(h[j]));
    }
    int node = seg >> 2;
    int r = seg & 3;
    size_t o = (size_t)node * KTOT + r * 128 + lane * 4;
    *reinterpret_cast<uint2*>(&g_ah[o]) = *reinterpret_cast<uint2*>(h);
    *reinterpret_cast<uint2*>(&g_al[o]) = *reinterpret_cast<uint2*>(lo);
}

// ---------------- HMMA GEMM, fp16 2-pass split, occupancy-2 ----------------
// smem: [0:512) bias
//       A tiles (double buffered): 1024 + buf*32768 : {Ah 16K, Al 16K}
//       B tile (single buffered):  1024 + 65536     : {Bh 16K}
#define SMEM_DYN (1024 + 2 * 32768 + 16384)   // 82944 -> 2 CTAs/SM

__global__ void __launch_bounds__(256, 2) k_gemm(int layer, const float* __restrict__ bias) {
    extern __shared__ char smem[];
    float* sBias = (float*)smem;
    uint32_t smem_u = smem_to_u32(smem);
    int tid = threadIdx.x;
    int wid = tid >> 5;
    int lane = tid & 31;
    int brow = blockIdx.x * 128;

    if (tid < 32) {
        float4 b = *reinterpret_cast<const float4*>(bias + tid * 4);
        *reinterpret_cast<float4*>(&sBias[tid * 4]) = b;
    }

    const __half* bh = g_bh + (size_t)layer * D * KTOT;

    // warp tile: 32 (m) x 64 (n)
    int wm = wid & 3;            // m0 = wm*32
    int wn = wid >> 2;           // n0 = wn*64
    int lrow = lane & 15;
    int kh16 = (lane >> 4) * 16;

    const uint32_t bBase = smem_u + 1024 + 65536;

    float acc[2][8][4];
#pragma unroll
    for (int t = 0; t < 2; t++)
#pragma unroll
        for (int q = 0; q < 8; q++)
#pragma unroll
            for (int j = 0; j < 4; j++) acc[t][q][j] = 0.f;

    auto load_A = [&](int c, int buf) {
        uint32_t base = smem_u + 1024 + buf * 32768;
        int kcol = c * 64;
#pragma unroll
        for (int it = 0; it < 4; it++) {
            int u = tid + it * 256;          // 0..1023
            int row = u >> 3;                // 0..127
            int c16 = u & 7;
            uint32_t off = row * 128 + c16 * 16;
            uint32_t sw = off ^ ((off >> 3) & 0x70);
            CP16(base + sw,         &g_ah[(size_t)(brow + row) * KTOT + kcol + c16 * 8]);
            CP16(base + 16384 + sw, &g_al[(size_t)(brow + row) * KTOT + kcol + c16 * 8]);
        }
        asm volatile("cp.async.commit_group;" ::: "memory");
    };
    auto load_B = [&](int c) {
        int kcol = c * 64;
#pragma unroll
        for (int it = 0; it < 4; it++) {
            int u = tid + it * 256;          // 0..1023 -> full 128 rows
            int row = u >> 3;
            int c16 = u & 7;
            uint32_t off = row * 128 + c16 * 16;
            uint32_t sw = off ^ ((off >> 3) & 0x70);
            CP16(bBase + sw, &bh[(size_t)row * KTOT + kcol + c16 * 8]);
        }
        asm volatile("cp.async.commit_group;" ::: "memory");
    };

    load_A(0, 0);
    load_B(0);

    for (int c = 0; c < NCHUNK; c++) {
        asm volatile("cp.async.wait_group 0;" ::: "memory");
        __syncthreads();
        if (c + 1 < NCHUNK) load_A(c + 1, (c + 1) & 1);   // A buffer (c+1)&1 is free

        uint32_t base = smem_u + 1024 + (c & 1) * 32768;
#pragma unroll
        for (int ks = 0; ks < 4; ks++) {
            int kb = ks * 32 + kh16;
            uint32_t ah[2][4], al[2][4], bhf[4][4];
#pragma unroll
            for (int t = 0; t < 2; t++) {
                int row = wm * 32 + t * 16 + lrow;
                uint32_t off = row * 128 + kb;
                ldsm_x4(ah[t], base + (off ^ ((off >> 3) & 0x70)));
            }
#pragma unroll
            for (int p = 0; p < 4; p++) {
                int row = wn * 64 + p * 16 + lrow;
                uint32_t off = row * 128 + kb;
                ldsm_x4(bhf[p], bBase + (off ^ ((off >> 3) & 0x70)));
            }
            // pass 0: Ah * Bh
#pragma unroll
            for (int t = 0; t < 2; t++)
#pragma unroll
                for (int p = 0; p < 4; p++) {
                    mma16816(acc[t][2 * p + 0], ah[t], bhf[p][0], bhf[p][2]);
                    mma16816(acc[t][2 * p + 1], ah[t], bhf[p][1], bhf[p][3]);
                }
            // pass 1: Al * Bh
#pragma unroll
            for (int t = 0; t < 2; t++) {
                int row = wm * 32 + t * 16 + lrow;
                uint32_t off = row * 128 + kb;
                ldsm_x4(al[t], base + 16384 + (off ^ ((off >> 3) & 0x70)));
            }
#pragma unroll
            for (int t = 0; t < 2; t++)
#pragma unroll
                for (int p = 0; p < 4; p++) {
                    mma16816(acc[t][2 * p + 0], al[t], bhf[p][0], bhf[p][2]);
                    mma16816(acc[t][2 * p + 1], al[t], bhf[p][1], bhf[p][3]);
                }
        }
        __syncthreads();                         // all warps done with B(c)
        if (c + 1 < NCHUNK) load_B(c + 1);       // refill single B buffer
    }

    // ---- epilogue: + bias, write to g_tmp ----
#pragma unroll
    for (int t = 0; t < 2; t++) {
        int mrow = brow + wm * 32 + t * 16 + (lane >> 2);
#pragma unroll
        for (int q = 0; q < 8; q++) {
            int col = wn * 64 + (q >> 1) * 16 + (q & 1) * 8 + 2 * (lane & 3);
            float bx = sBias[col], by = sBias[col + 1];
            if (mrow < N_NODES) {
                float2 o0 = make_float2(acc[t][q][0] + bx, acc[t][q][1] + by);
                *reinterpret_cast<float2*>(g_tmp + (size_t)mrow * D + col) = o0;
            }
            if (mrow + 8 < N_NODES) {
                float2 o1 = make_float2(acc[t][q][2] + bx, acc[t][q][3] + by);
                *reinterpret_cast<float2*>(g_tmp + (size_t)(mrow + 8) * D + col) = o1;
            }
        }
    }
}

// ---------------- epilogue: relu + residual + layernorm (+ fp16 self-cols) ----------------
__global__ void k_epi(const float* __restrict__ xin, const float* __restrict__ gamma,
                      const float* __restrict__ beta, float* __restrict__ xout,
                      int write_next) {
    int row = blockIdx.x * 8 + (threadIdx.x >> 5);
    if (row >= N_NODES) return;
    int lane = threadIdx.x & 31;
    float4 t = *reinterpret_cast<const float4*>(g_tmp + (size_t)row * D + lane * 4);
    float4 xr = *reinterpret_cast<const float4*>(xin + (size_t)row * D + lane * 4);
    float4 v;
    v.x = fmaxf(t.x, 0.f) + xr.x;
    v.y = fmaxf(t.y, 0.f) + xr.y;
    v.z = fmaxf(t.z, 0.f) + xr.z;
    v.w = fmaxf(t.w, 0.f) + xr.w;
    float s = v.x + v.y + v.z + v.w;
    float sq = v.x * v.x + v.y * v.y + v.z * v.z + v.w * v.w;
#pragma unroll
    for (int o = 16; o; o >>= 1) {
        s += __shfl_xor_sync(0xFFFFFFFFu, s, o);
        sq += __shfl_xor_sync(0xFFFFFFFFu, sq, o);
    }
    float mean = s * (1.0f / 128.0f);
    float var = sq * (1.0f / 128.0f) - mean * mean;
    float rs = rsqrtf(var + 1e-5f);
    float4 g = *reinterpret_cast<const float4*>(gamma + lane * 4);
    float4 b = *reinterpret_cast<const float4*>(beta + lane * 4);
    float4 o;
    o.x = (v.x - mean) * rs * g.x + b.x;
    o.y = (v.y - mean) * rs * g.y + b.y;
    o.z = (v.z - mean) * rs * g.z + b.z;
    o.w = (v.w - mean) * rs * g.w + b.w;
    *reinterpret_cast<float4*>(xout + (size_t)row * D + lane * 4) = o;
    if (write_next) {
        float vv[4] = {o.x, o.y, o.z, o.w};
        __half h[4], lo[4];
#pragma unroll
        for (int j = 0; j < 4; j++) {
            h[j] = __float2half_rn(vv[j]);
            lo[j] = __float2half_rn(vv[j] - __half2float(h[j]));
        }
        size_t oo = (size_t)row * KTOT + 512 + lane * 4;
        *reinterpret_cast<uint2*>(&g_ah[oo]) = *reinterpret_cast<uint2*>(h);
        *reinterpret_cast<uint2*>(&g_al[oo]) = *reinterpret_cast<uint2*>(lo);
    }
}

// ---------------- host launcher ----------------
extern "C" void kernel_launch(void* const* d_in, const int* in_sizes, int n_in,
                              void* d_out, int out_size) {
    const float* x     = (const float*)d_in[0];
    const int*   ei    = (const int*)d_in[1];
    const int*   et    = (const int*)d_in[2];
    const float* W     = (const float*)d_in[3];
    const float* root  = (const float*)d_in[4];
    const float* bias  = (const float*)d_in[5];
    const float* gamma = (const float*)d_in[6];
    const float* beta  = (const float*)d_in[7];
    float* out = (float*)d_out;

    const int* src = ei;
    const int* dst = ei + N_EDGES;

    float *px1 = nullptr, *px2 = nullptr;
    cudaGetSymbolAddress((void**)&px1, g_x1);
    cudaGetSymbolAddress((void**)&px2, g_x2);

    cudaFuncSetAttribute(k_gemm, cudaFuncAttributeMaxDynamicSharedMemorySize, SMEM_DYN);

    // CSR build (edge structure is layer-invariant)
    k_zero_cnt<<<(NSEG + 255) / 256, 256>>>();
    k_hist<<<(N_EDGES + 255) / 256, 256>>>(dst, et);
    int nb = (NSEG + 1023) / 1024;
    k_scan1<<<nb, 1024>>>();
    k_scan23<<<nb, 1024>>>(nb);
    k_scatter<<<(N_EDGES + 255) / 256, 256>>>(src, dst, et);

    // weight transpose + fp16
    k_bprep<<<(NLAYER * D * KTOT + 255) / 256, 256>>>(W, root);
    // self-cols for layer 0
    k_convx<<<(N_NODES + 7) / 8, 256>>>(x);

    const float* xin = x;
    for (int l = 0; l < NLAYER; l++) {
        k_agg<<<(NSEG + 7) / 8, 256>>>(xin);
        k_gemm<<<NTILES, 256, SMEM_DYN>>>(l, bias + (size_t)l * D);
        float* xout = (l == NLAYER - 1) ? out : ((l == 0) ? px1 : px2);
        k_epi<<<(N_NODES + 7) / 8, 256>>>(xin, gamma + (size_t)l * D,
                                          beta + (size_t)l * D, xout,
                                          l < NLAYER - 1 ? 1 : 0);
        xin = xout;
    }
}

// round 10
// speedup vs baseline: 1.6944x; 1.3123x over previous
#include <cuda_runtime.h>
#include <cuda_fp16.h>
#include <cstdint>

#define N_NODES 50000
#define N_EDGES 800000
#define D 128
#define R 4
#define NSEG (N_NODES * R)      // 200000
#define NLAYER 3
#define KTOT 640                // R*D + D
#define MPAD 50048              // 391 * 128
#define NTILES 391
#define NCHUNK 10               // K chunks of 64 fp16 (128B rows)

// ---------------- static device scratch ----------------
__device__ __align__(16) __half g_ah[(size_t)MPAD * KTOT];        // A fp16 [node][640]
__device__ __align__(16) __half g_bh[(size_t)NLAYER * D * KTOT];  // B fp16 [l][n][k]
__device__ float g_tmp[(size_t)N_NODES * D];     // GEMM output before epilogue
__device__ float g_x1[(size_t)N_NODES * D];
__device__ float g_x2[(size_t)N_NODES * D];
__device__ int   g_cnt[NSEG];
__device__ int   g_off[NSEG + 1];
__device__ int   g_cursor[NSEG];
__device__ int   g_bsum[256];
__device__ int   g_srcs[N_EDGES];

// ---------------- helpers ----------------
__device__ __forceinline__ uint32_t smem_to_u32(const void* p) {
    uint32_t a;
    asm("{ .reg .u64 t; cvta.to.shared.u64 t, %1; cvt.u32.u64 %0, t; }"
        : "=r"(a) : "l"(p));
    return a;
}

#define CP16(sm, gp) \
    asm volatile("cp.async.cg.shared.global [%0], [%1], 16;" :: "r"(sm), "l"(gp))

__device__ __forceinline__ void ldsm_x4(uint32_t* f, uint32_t addr) {
    asm volatile("ldmatrix.sync.aligned.m8n8.x4.shared.b16 {%0,%1,%2,%3}, [%4];"
                 : "=r"(f[0]), "=r"(f[1]), "=r"(f[2]), "=r"(f[3]) : "r"(addr));
}

__device__ __forceinline__ void mma16816(float* d, const uint32_t* a,
                                         uint32_t b0, uint32_t b1) {
    asm volatile(
        "mma.sync.aligned.m16n8k16.row.col.f32.f16.f16.f32 "
        "{%0,%1,%2,%3}, {%4,%5,%6,%7}, {%8,%9}, {%0,%1,%2,%3};"
        : "+f"(d[0]), "+f"(d[1]), "+f"(d[2]), "+f"(d[3])
        : "r"(a[0]), "r"(a[1]), "r"(a[2]), "r"(a[3]), "r"(b0), "r"(b1));
}

// ---------------- CSR build ----------------
__global__ void k_zero_cnt() {
    int i = blockIdx.x * blockDim.x + threadIdx.x;
    if (i < NSEG) g_cnt[i] = 0;
}

__global__ void k_hist(const int* __restrict__ dst, const int* __restrict__ et) {
    int e = blockIdx.x * blockDim.x + threadIdx.x;
    if (e < N_EDGES) atomicAdd(&g_cnt[dst[e] * R + et[e]], 1);
}

__global__ void k_scan1() {
    __shared__ int sh[1024];
    int t = threadIdx.x;
    int i = blockIdx.x * 1024 + t;
    int v = (i < NSEG) ? g_cnt[i] : 0;
    sh[t] = v;
    __syncthreads();
    for (int d = 1; d < 1024; d <<= 1) {
        int add = (t >= d) ? sh[t - d] : 0;
        __syncthreads();
        sh[t] += add;
        __syncthreads();
    }
    if (i < NSEG) g_off[i] = sh[t] - v;
    if (t == 1023) g_bsum[blockIdx.x] = sh[1023];
}

// fused scan2+scan3: every block redundantly scans the block sums
__global__ void k_scan23(int nb) {
    __shared__ int sh[256];
    int t = threadIdx.x;
    if (t < 256) sh[t] = (t < nb) ? g_bsum[t] : 0;
    __syncthreads();
    for (int d = 1; d < 256; d <<= 1) {
        int add = 0;
        if (t < 256 && t >= d) add = sh[t - d];
        __syncthreads();
        if (t < 256) sh[t] += add;
        __syncthreads();
    }
    int boff = (blockIdx.x > 0) ? sh[blockIdx.x - 1] : 0;
    int i = blockIdx.x * 1024 + t;
    if (i < NSEG) {
        int o = g_off[i] + boff;
        g_off[i] = o;
        g_cursor[i] = o;
    }
    if (i == 0) g_off[NSEG] = N_EDGES;
}

__global__ void k_scatter(const int* __restrict__ src, const int* __restrict__ dst,
                          const int* __restrict__ et) {
    int e = blockIdx.x * blockDim.x + threadIdx.x;
    if (e < N_EDGES) {
        int seg = dst[e] * R + et[e];
        int pos = atomicAdd(&g_cursor[seg], 1);
        g_srcs[pos] = src[e];
    }
}

// ---------------- weight prep: transpose + fp16 ----------------
__global__ void k_bprep(const float* __restrict__ W, const float* __restrict__ root) {
    int i = blockIdx.x * 256 + threadIdx.x;     // over NLAYER*D*KTOT
    if (i >= NLAYER * D * KTOT) return;
    int k = i % KTOT;
    int t = i / KTOT;
    int n = t % D;
    int l = t / D;
    float w;
    if (k < 512) {
        int r = k >> 7, din = k & 127;
        w = W[(((size_t)l * R + r) * D + din) * D + n];
    } else {
        w = root[((size_t)l * D + (k - 512)) * D + n];
    }
    g_bh[i] = __float2half_rn(w);
}

// ---------------- fill self-columns (512..639) of A from fp32 activations ----------------
__global__ void k_convx(const float* __restrict__ x) {
    int row = blockIdx.x * 8 + (threadIdx.x >> 5);
    if (row >= N_NODES) return;
    int lane = threadIdx.x & 31;
    float4 v = *reinterpret_cast<const float4*>(x + (size_t)row * D + lane * 4);
    __half h[4];
    h[0] = __float2half_rn(v.x);
    h[1] = __float2half_rn(v.y);
    h[2] = __float2half_rn(v.z);
    h[3] = __float2half_rn(v.w);
    size_t o = (size_t)row * KTOT + 512 + lane * 4;
    *reinterpret_cast<uint2*>(&g_ah[o]) = *reinterpret_cast<uint2*>(h);
}

// ---------------- segment-mean aggregation (warp per segment) -> fp16 ----------------
__global__ void k_agg(const float* __restrict__ x) {
    int seg = blockIdx.x * 8 + (threadIdx.x >> 5);
    if (seg >= NSEG) return;
    int lane = threadIdx.x & 31;
    int beg = g_off[seg];
    int end = g_off[seg + 1];
    float ax = 0.f, ay = 0.f, az = 0.f, aw = 0.f;
    for (int j = beg; j < end; j++) {
        int sn = g_srcs[j];
        float4 v = *reinterpret_cast<const float4*>(x + (size_t)sn * D + lane * 4);
        ax += v.x; ay += v.y; az += v.z; aw += v.w;
    }
    float inv = (end > beg) ? 1.0f / (float)(end - beg) : 0.0f;
    __half h[4];
    h[0] = __float2half_rn(ax * inv);
    h[1] = __float2half_rn(ay * inv);
    h[2] = __float2half_rn(az * inv);
    h[3] = __float2half_rn(aw * inv);
    int node = seg >> 2;
    int r = seg & 3;
    size_t o = (size_t)node * KTOT + r * 128 + lane * 4;
    *reinterpret_cast<uint2*>(&g_ah[o]) = *reinterpret_cast<uint2*>(h);
}

// ---------------- HMMA GEMM, pure fp16 1-pass, occupancy-2 ----------------
// smem: [0:512) bias
//       A tiles (double buffered): 1024 + buf*16384 : {Ah 16K}
//       B tile (single buffered):  1024 + 32768     : {Bh 16K}
#define SMEM_DYN (1024 + 2 * 16384 + 16384)   // 50176

__global__ void __launch_bounds__(256, 2) k_gemm(int layer, const float* __restrict__ bias) {
    extern __shared__ char smem[];
    float* sBias = (float*)smem;
    uint32_t smem_u = smem_to_u32(smem);
    int tid = threadIdx.x;
    int wid = tid >> 5;
    int lane = tid & 31;
    int brow = blockIdx.x * 128;

    if (tid < 32) {
        float4 b = *reinterpret_cast<const float4*>(bias + tid * 4);
        *reinterpret_cast<float4*>(&sBias[tid * 4]) = b;
    }

    const __half* bh = g_bh + (size_t)layer * D * KTOT;

    // warp tile: 32 (m) x 64 (n)
    int wm = wid & 3;            // m0 = wm*32
    int wn = wid >> 2;           // n0 = wn*64
    int lrow = lane & 15;
    int kh16 = (lane >> 4) * 16;

    const uint32_t bBase = smem_u + 1024 + 32768;

    float acc[2][8][4];
#pragma unroll
    for (int t = 0; t < 2; t++)
#pragma unroll
        for (int q = 0; q < 8; q++)
#pragma unroll
            for (int j = 0; j < 4; j++) acc[t][q][j] = 0.f;

    auto load_A = [&](int c, int buf) {
        uint32_t base = smem_u + 1024 + buf * 16384;
        int kcol = c * 64;
#pragma unroll
        for (int it = 0; it < 4; it++) {
            int u = tid + it * 256;          // 0..1023
            int row = u >> 3;                // 0..127
            int c16 = u & 7;
            uint32_t off = row * 128 + c16 * 16;
            uint32_t sw = off ^ ((off >> 3) & 0x70);
            CP16(base + sw, &g_ah[(size_t)(brow + row) * KTOT + kcol + c16 * 8]);
        }
        asm volatile("cp.async.commit_group;" ::: "memory");
    };
    auto load_B = [&](int c) {
        int kcol = c * 64;
#pragma unroll
        for (int it = 0; it < 4; it++) {
            int u = tid + it * 256;          // 0..1023 -> full 128 rows
            int row = u >> 3;
            int c16 = u & 7;
            uint32_t off = row * 128 + c16 * 16;
            uint32_t sw = off ^ ((off >> 3) & 0x70);
            CP16(bBase + sw, &bh[(size_t)row * KTOT + kcol + c16 * 8]);
        }
        asm volatile("cp.async.commit_group;" ::: "memory");
    };

    load_A(0, 0);
    load_B(0);

    for (int c = 0; c < NCHUNK; c++) {
        asm volatile("cp.async.wait_group 0;" ::: "memory");
        __syncthreads();
        if (c + 1 < NCHUNK) load_A(c + 1, (c + 1) & 1);   // A buffer (c+1)&1 is free

        uint32_t base = smem_u + 1024 + (c & 1) * 16384;
#pragma unroll
        for (int ks = 0; ks < 4; ks++) {
            int kb = ks * 32 + kh16;
            uint32_t ah[2][4], bhf[4][4];
#pragma unroll
            for (int t = 0; t < 2; t++) {
                int row = wm * 32 + t * 16 + lrow;
                uint32_t off = row * 128 + kb;
                ldsm_x4(ah[t], base + (off ^ ((off >> 3) & 0x70)));
            }
#pragma unroll
            for (int p = 0; p < 4; p++) {
                int row = wn * 64 + p * 16 + lrow;
                uint32_t off = row * 128 + kb;
                ldsm_x4(bhf[p], bBase + (off ^ ((off >> 3) & 0x70)));
            }
#pragma unroll
            for (int t = 0; t < 2; t++)
#pragma unroll
                for (int p = 0; p < 4; p++) {
                    mma16816(acc[t][2 * p + 0], ah[t], bhf[p][0], bhf[p][2]);
                    mma16816(acc[t][2 * p + 1], ah[t], bhf[p][1], bhf[p][3]);
                }
        }
        __syncthreads();                         // all warps done with B(c)
        if (c + 1 < NCHUNK) load_B(c + 1);       // refill single B buffer
    }

    // ---- epilogue: + bias, write to g_tmp ----
#pragma unroll
    for (int t = 0; t < 2; t++) {
        int mrow = brow + wm * 32 + t * 16 + (lane >> 2);
#pragma unroll
        for (int q = 0; q < 8; q++) {
            int col = wn * 64 + (q >> 1) * 16 + (q & 1) * 8 + 2 * (lane & 3);
            float bx = sBias[col], by = sBias[col + 1];
            if (mrow < N_NODES) {
                float2 o0 = make_float2(acc[t][q][0] + bx, acc[t][q][1] + by);
                *reinterpret_cast<float2*>(g_tmp + (size_t)mrow * D + col) = o0;
            }
            if (mrow + 8 < N_NODES) {
                float2 o1 = make_float2(acc[t][q][2] + bx, acc[t][q][3] + by);
                *reinterpret_cast<float2*>(g_tmp + (size_t)(mrow + 8) * D + col) = o1;
            }
        }
    }
}

// ---------------- epilogue: relu + residual + layernorm (+ fp16 self-cols) ----------------
__global__ void k_epi(const float* __restrict__ xin, const float* __restrict__ gamma,
                      const float* __restrict__ beta, float* __restrict__ xout,
                      int write_next) {
    int row = blockIdx.x * 8 + (threadIdx.x >> 5);
    if (row >= N_NODES) return;
    int lane = threadIdx.x & 31;
    float4 t = *reinterpret_cast<const float4*>(g_tmp + (size_t)row * D + lane * 4);
    float4 xr = *reinterpret_cast<const float4*>(xin + (size_t)row * D + lane * 4);
    float4 v;
    v.x = fmaxf(t.x, 0.f) + xr.x;
    v.y = fmaxf(t.y, 0.f) + xr.y;
    v.z = fmaxf(t.z, 0.f) + xr.z;
    v.w = fmaxf(t.w, 0.f) + xr.w;
    float s = v.x + v.y + v.z + v.w;
    float sq = v.x * v.x + v.y * v.y + v.z * v.z + v.w * v.w;
#pragma unroll
    for (int o = 16; o; o >>= 1) {
        s += __shfl_xor_sync(0xFFFFFFFFu, s, o);
        sq += __shfl_xor_sync(0xFFFFFFFFu, sq, o);
    }
    float mean = s * (1.0f / 128.0f);
    float var = sq * (1.0f / 128.0f) - mean * mean;
    float rs = rsqrtf(var + 1e-5f);
    float4 g = *reinterpret_cast<const float4*>(gamma + lane * 4);
    float4 b = *reinterpret_cast<const float4*>(beta + lane * 4);
    float4 o;
    o.x = (v.x - mean) * rs * g.x + b.x;
    o.y = (v.y - mean) * rs * g.y + b.y;
    o.z = (v.z - mean) * rs * g.z + b.z;
    o.w = (v.w - mean) * rs * g.w + b.w;
    *reinterpret_cast<float4*>(xout + (size_t)row * D + lane * 4) = o;
    if (write_next) {
        __half h[4];
        h[0] = __float2half_rn(o.x);
        h[1] = __float2half_rn(o.y);
        h[2] = __float2half_rn(o.z);
        h[3] = __float2half_rn(o.w);
        size_t oo = (size_t)row * KTOT + 512 + lane * 4;
        *reinterpret_cast<uint2*>(&g_ah[oo]) = *reinterpret_cast<uint2*>(h);
    }
}

// ---------------- host launcher ----------------
extern "C" void kernel_launch(void* const* d_in, const int* in_sizes, int n_in,
                              void* d_out, int out_size) {
    const float* x     = (const float*)d_in[0];
    const int*   ei    = (const int*)d_in[1];
    const int*   et    = (const int*)d_in[2];
    const float* W     = (const float*)d_in[3];
    const float* root  = (const float*)d_in[4];
    const float* bias  = (const float*)d_in[5];
    const float* gamma = (const float*)d_in[6];
    const float* beta  = (const float*)d_in[7];
    float* out = (float*)d_out;

    const int* src = ei;
    const int* dst = ei + N_EDGES;

    float *px1 = nullptr, *px2 = nullptr;
    cudaGetSymbolAddress((void**)&px1, g_x1);
    cudaGetSymbolAddress((void**)&px2, g_x2);

    cudaFuncSetAttribute(k_gemm, cudaFuncAttributeMaxDynamicSharedMemorySize, SMEM_DYN);

    // CSR build (edge structure is layer-invariant)
    k_zero_cnt<<<(NSEG + 255) / 256, 256>>>();
    k_hist<<<(N_EDGES + 255) / 256, 256>>>(dst, et);
    int nb = (NSEG + 1023) / 1024;
    k_scan1<<<nb, 1024>>>();
    k_scan23<<<nb, 1024>>>(nb);
    k_scatter<<<(N_EDGES + 255) / 256, 256>>>(src, dst, et);

    // weight transpose + fp16
    k_bprep<<<(NLAYER * D * KTOT + 255) / 256, 256>>>(W, root);
    // self-cols for layer 0
    k_convx<<<(N_NODES + 7) / 8, 256>>>(x);

    const float* xin = x;
    for (int l = 0; l < NLAYER; l++) {
        k_agg<<<(NSEG + 7) / 8, 256>>>(xin);
        k_gemm<<<NTILES, 256, SMEM_DYN>>>(l, bias + (size_t)l * D);
        float* xout = (l == NLAYER - 1) ? out : ((l == 0) ? px1 : px2);
        k_epi<<<(N_NODES + 7) / 8, 256>>>(xin, gamma + (size_t)l * D,
                                          beta + (size_t)l * D, xout,
                                          l < NLAYER - 1 ? 1 : 0);
        xin = xout;
    }
}

// round 11
// speedup vs baseline: 1.7013x; 1.0041x over previous
#include <cuda_runtime.h>
#include <cuda_fp16.h>
#include <cstdint>

#define N_NODES 50000
#define N_EDGES 800000
#define D 128
#define R 4
#define NSEG (N_NODES * R)      // 200000
#define NLAYER 3
#define KTOT 640                // R*D + D
#define MPAD 50048              // 391 * 128
#define NTILES 391
#define NCHUNK 10               // K chunks of 64 fp16 (128B rows)

// ---------------- static device scratch ----------------
__device__ __align__(16) __half g_ah[(size_t)MPAD * KTOT];        // A fp16 [node][640]
__device__ __align__(16) __half g_bh[(size_t)NLAYER * D * KTOT];  // B fp16 [l][n][k]
__device__ float g_tmp[(size_t)N_NODES * D];     // GEMM output before epilogue
__device__ float g_x1[(size_t)N_NODES * D];
__device__ float g_x2[(size_t)N_NODES * D];
__device__ int   g_cnt[NSEG];
__device__ int   g_off[NSEG + 1];
__device__ int   g_cursor[NSEG];
__device__ int   g_bsum[256];
__device__ int   g_srcs[N_EDGES];

// ---------------- helpers ----------------
__device__ __forceinline__ uint32_t smem_to_u32(const void* p) {
    uint32_t a;
    asm("{ .reg .u64 t; cvta.to.shared.u64 t, %1; cvt.u32.u64 %0, t; }"
        : "=r"(a) : "l"(p));
    return a;
}

#define CP16(sm, gp) \
    asm volatile("cp.async.cg.shared.global [%0], [%1], 16;" :: "r"(sm), "l"(gp))

__device__ __forceinline__ void ldsm_x4(uint32_t* f, uint32_t addr) {
    asm volatile("ldmatrix.sync.aligned.m8n8.x4.shared.b16 {%0,%1,%2,%3}, [%4];"
                 : "=r"(f[0]), "=r"(f[1]), "=r"(f[2]), "=r"(f[3]) : "r"(addr));
}

__device__ __forceinline__ void mma16816(float* d, const uint32_t* a,
                                         uint32_t b0, uint32_t b1) {
    asm volatile(
        "mma.sync.aligned.m16n8k16.row.col.f32.f16.f16.f32 "
        "{%0,%1,%2,%3}, {%4,%5,%6,%7}, {%8,%9}, {%0,%1,%2,%3};"
        : "+f"(d[0]), "+f"(d[1]), "+f"(d[2]), "+f"(d[3])
        : "r"(a[0]), "r"(a[1]), "r"(a[2]), "r"(a[3]), "r"(b0), "r"(b1));
}

// ---------------- CSR build ----------------
__global__ void k_zero_cnt() {
    int i = blockIdx.x * blockDim.x + threadIdx.x;
    if (i < NSEG) g_cnt[i] = 0;
}

__global__ void k_hist(const int* __restrict__ dst, const int* __restrict__ et) {
    int e = blockIdx.x * blockDim.x + threadIdx.x;
    if (e < N_EDGES) atomicAdd(&g_cnt[dst[e] * R + et[e]], 1);
}

__global__ void k_scan1() {
    __shared__ int sh[1024];
    int t = threadIdx.x;
    int i = blockIdx.x * 1024 + t;
    int v = (i < NSEG) ? g_cnt[i] : 0;
    sh[t] = v;
    __syncthreads();
    for (int d = 1; d < 1024; d <<= 1) {
        int add = (t >= d) ? sh[t - d] : 0;
        __syncthreads();
        sh[t] += add;
        __syncthreads();
    }
    if (i < NSEG) g_off[i] = sh[t] - v;
    if (t == 1023) g_bsum[blockIdx.x] = sh[1023];
}

// fused scan2+scan3: every block redundantly scans the block sums
__global__ void k_scan23(int nb) {
    __shared__ int sh[256];
    int t = threadIdx.x;
    if (t < 256) sh[t] = (t < nb) ? g_bsum[t] : 0;
    __syncthreads();
    for (int d = 1; d < 256; d <<= 1) {
        int add = 0;
        if (t < 256 && t >= d) add = sh[t - d];
        __syncthreads();
        if (t < 256) sh[t] += add;
        __syncthreads();
    }
    int boff = (blockIdx.x > 0) ? sh[blockIdx.x - 1] : 0;
    int i = blockIdx.x * 1024 + t;
    if (i < NSEG) {
        int o = g_off[i] + boff;
        g_off[i] = o;
        g_cursor[i] = o;
    }
    if (i == 0) g_off[NSEG] = N_EDGES;
}

__global__ void k_scatter(const int* __restrict__ src, const int* __restrict__ dst,
                          const int* __restrict__ et) {
    int e = blockIdx.x * blockDim.x + threadIdx.x;
    if (e < N_EDGES) {
        int seg = dst[e] * R + et[e];
        int pos = atomicAdd(&g_cursor[seg], 1);
        g_srcs[pos] = src[e];
    }
}

// ---------------- weight prep: transpose + fp16 ----------------
__global__ void k_bprep(const float* __restrict__ W, const float* __restrict__ root) {
    int i = blockIdx.x * 256 + threadIdx.x;     // over NLAYER*D*KTOT
    if (i >= NLAYER * D * KTOT) return;
    int k = i % KTOT;
    int t = i / KTOT;
    int n = t % D;
    int l = t / D;
    float w;
    if (k < 512) {
        int r = k >> 7, din = k & 127;
        w = W[(((size_t)l * R + r) * D + din) * D + n];
    } else {
        w = root[((size_t)l * D + (k - 512)) * D + n];
    }
    g_bh[i] = __float2half_rn(w);
}

// ---------------- fill self-columns (512..639) of A from fp32 activations ----------------
__global__ void k_convx(const float* __restrict__ x) {
    int row = blockIdx.x * 8 + (threadIdx.x >> 5);
    if (row >= N_NODES) return;
    int lane = threadIdx.x & 31;
    float4 v = *reinterpret_cast<const float4*>(x + (size_t)row * D + lane * 4);
    __half h[4];
    h[0] = __float2half_rn(v.x);
    h[1] = __float2half_rn(v.y);
    h[2] = __float2half_rn(v.z);
    h[3] = __float2half_rn(v.w);
    size_t o = (size_t)row * KTOT + 512 + lane * 4;
    *reinterpret_cast<uint2*>(&g_ah[o]) = *reinterpret_cast<uint2*>(h);
}

// ---------------- segment-mean aggregation (warp per segment) ----------------
// Gathers fp16 activations from the self-columns of g_ah (256 B/edge instead of
// 512 B/edge fp32) and accumulates in fp32.
__global__ void k_agg() {
    int seg = blockIdx.x * 8 + (threadIdx.x >> 5);
    if (seg >= NSEG) return;
    int lane = threadIdx.x & 31;
    int beg = g_off[seg];
    int end = g_off[seg + 1];
    float ax = 0.f, ay = 0.f, az = 0.f, aw = 0.f;
    for (int j = beg; j < end; j++) {
        int sn = g_srcs[j];
        uint2 raw = *reinterpret_cast<const uint2*>(
            &g_ah[(size_t)sn * KTOT + 512 + lane * 4]);
        __half2 h01 = *reinterpret_cast<__half2*>(&raw.x);
        __half2 h23 = *reinterpret_cast<__half2*>(&raw.y);
        float2 f01 = __half22float2(h01);
        float2 f23 = __half22float2(h23);
        ax += f01.x; ay += f01.y; az += f23.x; aw += f23.y;
    }
    float inv = (end > beg) ? 1.0f / (float)(end - beg) : 0.0f;
    __half h[4];
    h[0] = __float2half_rn(ax * inv);
    h[1] = __float2half_rn(ay * inv);
    h[2] = __float2half_rn(az * inv);
    h[3] = __float2half_rn(aw * inv);
    int node = seg >> 2;
    int r = seg & 3;
    size_t o = (size_t)node * KTOT + r * 128 + lane * 4;
    *reinterpret_cast<uint2*>(&g_ah[o]) = *reinterpret_cast<uint2*>(h);
}

// ---------------- HMMA GEMM, pure fp16 1-pass, occupancy-2 ----------------
// smem: [0:512) bias
//       A tiles (double buffered): 1024 + buf*16384 : {Ah 16K}
//       B tile (single buffered):  1024 + 32768     : {Bh 16K}
#define SMEM_DYN (1024 + 2 * 16384 + 16384)   // 50176

__global__ void __launch_bounds__(256, 2) k_gemm(int layer, const float* __restrict__ bias) {
    extern __shared__ char smem[];
    float* sBias = (float*)smem;
    uint32_t smem_u = smem_to_u32(smem);
    int tid = threadIdx.x;
    int wid = tid >> 5;
    int lane = tid & 31;
    int brow = blockIdx.x * 128;

    if (tid < 32) {
        float4 b = *reinterpret_cast<const float4*>(bias + tid * 4);
        *reinterpret_cast<float4*>(&sBias[tid * 4]) = b;
    }

    const __half* bh = g_bh + (size_t)layer * D * KTOT;

    // warp tile: 32 (m) x 64 (n)
    int wm = wid & 3;            // m0 = wm*32
    int wn = wid >> 2;           // n0 = wn*64
    int lrow = lane & 15;
    int kh16 = (lane >> 4) * 16;

    const uint32_t bBase = smem_u + 1024 + 32768;

    float acc[2][8][4];
#pragma unroll
    for (int t = 0; t < 2; t++)
#pragma unroll
        for (int q = 0; q < 8; q++)
#pragma unroll
            for (int j = 0; j < 4; j++) acc[t][q][j] = 0.f;

    auto load_A = [&](int c, int buf) {
        uint32_t base = smem_u + 1024 + buf * 16384;
        int kcol = c * 64;
#pragma unroll
        for (int it = 0; it < 4; it++) {
            int u = tid + it * 256;          // 0..1023
            int row = u >> 3;                // 0..127
            int c16 = u & 7;
            uint32_t off = row * 128 + c16 * 16;
            uint32_t sw = off ^ ((off >> 3) & 0x70);
            CP16(base + sw, &g_ah[(size_t)(brow + row) * KTOT + kcol + c16 * 8]);
        }
        asm volatile("cp.async.commit_group;" ::: "memory");
    };
    auto load_B = [&](int c) {
        int kcol = c * 64;
#pragma unroll
        for (int it = 0; it < 4; it++) {
            int u = tid + it * 256;          // 0..1023 -> full 128 rows
            int row = u >> 3;
            int c16 = u & 7;
            uint32_t off = row * 128 + c16 * 16;
            uint32_t sw = off ^ ((off >> 3) & 0x70);
            CP16(bBase + sw, &bh[(size_t)row * KTOT + kcol + c16 * 8]);
        }
        asm volatile("cp.async.commit_group;" ::: "memory");
    };

    load_A(0, 0);
    load_B(0);

    for (int c = 0; c < NCHUNK; c++) {
        asm volatile("cp.async.wait_group 0;" ::: "memory");
        __syncthreads();
        if (c + 1 < NCHUNK) load_A(c + 1, (c + 1) & 1);   // A buffer (c+1)&1 is free

        uint32_t base = smem_u + 1024 + (c & 1) * 16384;
#pragma unroll
        for (int ks = 0; ks < 4; ks++) {
            int kb = ks * 32 + kh16;
            uint32_t ah[2][4], bhf[4][4];
#pragma unroll
            for (int t = 0; t < 2; t++) {
                int row = wm * 32 + t * 16 + lrow;
                uint32_t off = row * 128 + kb;
                ldsm_x4(ah[t], base + (off ^ ((off >> 3) & 0x70)));
            }
#pragma unroll
            for (int p = 0; p < 4; p++) {
                int row = wn * 64 + p * 16 + lrow;
                uint32_t off = row * 128 + kb;
                ldsm_x4(bhf[p], bBase + (off ^ ((off >> 3) & 0x70)));
            }
#pragma unroll
            for (int t = 0; t < 2; t++)
#pragma unroll
                for (int p = 0; p < 4; p++) {
                    mma16816(acc[t][2 * p + 0], ah[t], bhf[p][0], bhf[p][2]);
                    mma16816(acc[t][2 * p + 1], ah[t], bhf[p][1], bhf[p][3]);
                }
        }
        __syncthreads();                         // all warps done with B(c)
        if (c + 1 < NCHUNK) load_B(c + 1);       // refill single B buffer
    }

    // ---- epilogue: + bias, write to g_tmp ----
#pragma unroll
    for (int t = 0; t < 2; t++) {
        int mrow = brow + wm * 32 + t * 16 + (lane >> 2);
#pragma unroll
        for (int q = 0; q < 8; q++) {
            int col = wn * 64 + (q >> 1) * 16 + (q & 1) * 8 + 2 * (lane & 3);
            float bx = sBias[col], by = sBias[col + 1];
            if (mrow < N_NODES) {
                float2 o0 = make_float2(acc[t][q][0] + bx, acc[t][q][1] + by);
                *reinterpret_cast<float2*>(g_tmp + (size_t)mrow * D + col) = o0;
            }
            if (mrow + 8 < N_NODES) {
                float2 o1 = make_float2(acc[t][q][2] + bx, acc[t][q][3] + by);
                *reinterpret_cast<float2*>(g_tmp + (size_t)(mrow + 8) * D + col) = o1;
            }
        }
    }
}

// ---------------- epilogue: relu + residual + layernorm (+ fp16 self-cols) ----------------
__global__ void k_epi(const float* __restrict__ xin, const float* __restrict__ gamma,
                      const float* __restrict__ beta, float* __restrict__ xout,
                      int write_next) {
    int row = blockIdx.x * 8 + (threadIdx.x >> 5);
    if (row >= N_NODES) return;
    int lane = threadIdx.x & 31;
    float4 t = *reinterpret_cast<const float4*>(g_tmp + (size_t)row * D + lane * 4);
    float4 xr = *reinterpret_cast<const float4*>(xin + (size_t)row * D + lane * 4);
    float4 v;
    v.x = fmaxf(t.x, 0.f) + xr.x;
    v.y = fmaxf(t.y, 0.f) + xr.y;
    v.z = fmaxf(t.z, 0.f) + xr.z;
    v.w = fmaxf(t.w, 0.f) + xr.w;
    float s = v.x + v.y + v.z + v.w;
    float sq = v.x * v.x + v.y * v.y + v.z * v.z + v.w * v.w;
#pragma unroll
    for (int o = 16; o; o >>= 1) {
        s += __shfl_xor_sync(0xFFFFFFFFu, s, o);
        sq += __shfl_xor_sync(0xFFFFFFFFu, sq, o);
    }
    float mean = s * (1.0f / 128.0f);
    float var = sq * (1.0f / 128.0f) - mean * mean;
    float rs = rsqrtf(var + 1e-5f);
    float4 g = *reinterpret_cast<const float4*>(gamma + lane * 4);
    float4 b = *reinterpret_cast<const float4*>(beta + lane * 4);
    float4 o;
    o.x = (v.x - mean) * rs * g.x + b.x;
    o.y = (v.y - mean) * rs * g.y + b.y;
    o.z = (v.z - mean) * rs * g.z + b.z;
    o.w = (v.w - mean) * rs * g.w + b.w;
    *reinterpret_cast<float4*>(xout + (size_t)row * D + lane * 4) = o;
    if (write_next) {
        __half h[4];
        h[0] = __float2half_rn(o.x);
        h[1] = __float2half_rn(o.y);
        h[2] = __float2half_rn(o.z);
        h[3] = __float2half_rn(o.w);
        size_t oo = (size_t)row * KTOT + 512 + lane * 4;
        *reinterpret_cast<uint2*>(&g_ah[oo]) = *reinterpret_cast<uint2*>(h);
    }
}

// ---------------- host launcher ----------------
extern "C" void kernel_launch(void* const* d_in, const int* in_sizes, int n_in,
                              void* d_out, int out_size) {
    const float* x     = (const float*)d_in[0];
    const int*   ei    = (const int*)d_in[1];
    const int*   et    = (const int*)d_in[2];
    const float* W     = (const float*)d_in[3];
    const float* root  = (const float*)d_in[4];
    const float* bias  = (const float*)d_in[5];
    const float* gamma = (const float*)d_in[6];
    const float* beta  = (const float*)d_in[7];
    float* out = (float*)d_out;

    const int* src = ei;
    const int* dst = ei + N_EDGES;

    float *px1 = nullptr, *px2 = nullptr;
    cudaGetSymbolAddress((void**)&px1, g_x1);
    cudaGetSymbolAddress((void**)&px2, g_x2);

    cudaFuncSetAttribute(k_gemm, cudaFuncAttributeMaxDynamicSharedMemorySize, SMEM_DYN);

    // CSR build (edge structure is layer-invariant)
    k_zero_cnt<<<(NSEG + 255) / 256, 256>>>();
    k_hist<<<(N_EDGES + 255) / 256, 256>>>(dst, et);
    int nb = (NSEG + 1023) / 1024;
    k_scan1<<<nb, 1024>>>();
    k_scan23<<<nb, 1024>>>(nb);
    k_scatter<<<(N_EDGES + 255) / 256, 256>>>(src, dst, et);

    // weight transpose + fp16
    k_bprep<<<(NLAYER * D * KTOT + 255) / 256, 256>>>(W, root);
    // self-cols for layer 0 (must precede first k_agg — it gathers from them)
    k_convx<<<(N_NODES + 7) / 8, 256>>>(x);

    const float* xin = x;
    for (int l = 0; l < NLAYER; l++) {
        k_agg<<<(NSEG + 7) / 8, 256>>>();
        k_gemm<<<NTILES, 256, SMEM_DYN>>>(l, bias + (size_t)l * D);
        float* xout = (l == NLAYER - 1) ? out : ((l == 0) ? px1 : px2);
        k_epi<<<(N_NODES + 7) / 8, 256>>>(xin, gamma + (size_t)l * D,
                                          beta + (size_t)l * D, xout,
                                          l < NLAYER - 1 ? 1 : 0);
        xin = xout;
    }
}

// round 12
// speedup vs baseline: 1.7162x; 1.0088x over previous
#include <cuda_runtime.h>
#include <cuda_fp16.h>
#include <cstdint>

#define N_NODES 50000
#define N_EDGES 800000
#define D 128
#define R 4
#define NSEG (N_NODES * R)      // 200000
#define NLAYER 3
#define KTOT 640                // R*D + D
#define MPAD 50048              // 391 * 128
#define NTILES 391
#define NCHUNK 10               // K chunks of 64 fp16 (128B rows)

// ---------------- static device scratch ----------------
__device__ __align__(16) __half g_ah[(size_t)MPAD * KTOT];        // A fp16 [node][640]
__device__ __align__(16) __half g_bh[(size_t)NLAYER * D * KTOT];  // B fp16 [l][n][k]
__device__ float g_x1[(size_t)N_NODES * D];
__device__ float g_x2[(size_t)N_NODES * D];
__device__ int   g_cnt[NSEG];
__device__ int   g_off[NSEG + 1];
__device__ int   g_cursor[NSEG];
__device__ int   g_bsum[256];
__device__ int   g_srcs[N_EDGES];

// ---------------- helpers ----------------
__device__ __forceinline__ uint32_t smem_to_u32(const void* p) {
    uint32_t a;
    asm("{ .reg .u64 t; cvta.to.shared.u64 t, %1; cvt.u32.u64 %0, t; }"
        : "=r"(a) : "l"(p));
    return a;
}

#define CP16(sm, gp) \
    asm volatile("cp.async.cg.shared.global [%0], [%1], 16;" :: "r"(sm), "l"(gp))

__device__ __forceinline__ void ldsm_x4(uint32_t* f, uint32_t addr) {
    asm volatile("ldmatrix.sync.aligned.m8n8.x4.shared.b16 {%0,%1,%2,%3}, [%4];"
                 : "=r"(f[0]), "=r"(f[1]), "=r"(f[2]), "=r"(f[3]) : "r"(addr));
}

__device__ __forceinline__ void mma16816(float* d, const uint32_t* a,
                                         uint32_t b0, uint32_t b1) {
    asm volatile(
        "mma.sync.aligned.m16n8k16.row.col.f32.f16.f16.f32 "
        "{%0,%1,%2,%3}, {%4,%5,%6,%7}, {%8,%9}, {%0,%1,%2,%3};"
        : "+f"(d[0]), "+f"(d[1]), "+f"(d[2]), "+f"(d[3])
        : "r"(a[0]), "r"(a[1]), "r"(a[2]), "r"(a[3]), "r"(b0), "r"(b1));
}

// ---------------- CSR build ----------------
__global__ void k_zero_cnt() {
    int i = blockIdx.x * blockDim.x + threadIdx.x;
    if (i < NSEG) g_cnt[i] = 0;
}

__global__ void k_hist(const int* __restrict__ dst, const int* __restrict__ et) {
    int e = blockIdx.x * blockDim.x + threadIdx.x;
    if (e < N_EDGES) atomicAdd(&g_cnt[dst[e] * R + et[e]], 1);
}

__global__ void k_scan1() {
    __shared__ int sh[1024];
    int t = threadIdx.x;
    int i = blockIdx.x * 1024 + t;
    int v = (i < NSEG) ? g_cnt[i] : 0;
    sh[t] = v;
    __syncthreads();
    for (int d = 1; d < 1024; d <<= 1) {
        int add = (t >= d) ? sh[t - d] : 0;
        __syncthreads();
        sh[t] += add;
        __syncthreads();
    }
    if (i < NSEG) g_off[i] = sh[t] - v;
    if (t == 1023) g_bsum[blockIdx.x] = sh[1023];
}

// fused scan2+scan3: every block redundantly scans the block sums
__global__ void k_scan23(int nb) {
    __shared__ int sh[256];
    int t = threadIdx.x;
    if (t < 256) sh[t] = (t < nb) ? g_bsum[t] : 0;
    __syncthreads();
    for (int d = 1; d < 256; d <<= 1) {
        int add = 0;
        if (t < 256 && t >= d) add = sh[t - d];
        __syncthreads();
        if (t < 256) sh[t] += add;
        __syncthreads();
    }
    int boff = (blockIdx.x > 0) ? sh[blockIdx.x - 1] : 0;
    int i = blockIdx.x * 1024 + t;
    if (i < NSEG) {
        int o = g_off[i] + boff;
        g_off[i] = o;
        g_cursor[i] = o;
    }
    if (i == 0) g_off[NSEG] = N_EDGES;
}

__global__ void k_scatter(const int* __restrict__ src, const int* __restrict__ dst,
                          const int* __restrict__ et) {
    int e = blockIdx.x * blockDim.x + threadIdx.x;
    if (e < N_EDGES) {
        int seg = dst[e] * R + et[e];
        int pos = atomicAdd(&g_cursor[seg], 1);
        g_srcs[pos] = src[e];
    }
}

// ---------------- weight prep: transpose + fp16 ----------------
__global__ void k_bprep(const float* __restrict__ W, const float* __restrict__ root) {
    int i = blockIdx.x * 256 + threadIdx.x;     // over NLAYER*D*KTOT
    if (i >= NLAYER * D * KTOT) return;
    int k = i % KTOT;
    int t = i / KTOT;
    int n = t % D;
    int l = t / D;
    float w;
    if (k < 512) {
        int r = k >> 7, din = k & 127;
        w = W[(((size_t)l * R + r) * D + din) * D + n];
    } else {
        w = root[((size_t)l * D + (k - 512)) * D + n];
    }
    g_bh[i] = __float2half_rn(w);
}

// ---------------- fill self-columns (512..639) of A from fp32 activations ----------------
__global__ void k_convx(const float* __restrict__ x) {
    int row = blockIdx.x * 8 + (threadIdx.x >> 5);
    if (row >= N_NODES) return;
    int lane = threadIdx.x & 31;
    float4 v = *reinterpret_cast<const float4*>(x + (size_t)row * D + lane * 4);
    __half h[4];
    h[0] = __float2half_rn(v.x);
    h[1] = __float2half_rn(v.y);
    h[2] = __float2half_rn(v.z);
    h[3] = __float2half_rn(v.w);
    size_t o = (size_t)row * KTOT + 512 + lane * 4;
    *reinterpret_cast<uint2*>(&g_ah[o]) = *reinterpret_cast<uint2*>(h);
}

// ---------------- segment-mean aggregation (warp per segment) ----------------
__global__ void k_agg() {
    int seg = blockIdx.x * 8 + (threadIdx.x >> 5);
    if (seg >= NSEG) return;
    int lane = threadIdx.x & 31;
    int beg = g_off[seg];
    int end = g_off[seg + 1];
    float ax = 0.f, ay = 0.f, az = 0.f, aw = 0.f;
    for (int j = beg; j < end; j++) {
        int sn = g_srcs[j];
        uint2 raw = *reinterpret_cast<const uint2*>(
            &g_ah[(size_t)sn * KTOT + 512 + lane * 4]);
        __half2 h01 = *reinterpret_cast<__half2*>(&raw.x);
        __half2 h23 = *reinterpret_cast<__half2*>(&raw.y);
        float2 f01 = __half22float2(h01);
        float2 f23 = __half22float2(h23);
        ax += f01.x; ay += f01.y; az += f23.x; aw += f23.y;
    }
    float inv = (end > beg) ? 1.0f / (float)(end - beg) : 0.0f;
    __half h[4];
    h[0] = __float2half_rn(ax * inv);
    h[1] = __float2half_rn(ay * inv);
    h[2] = __float2half_rn(az * inv);
    h[3] = __float2half_rn(aw * inv);
    int node = seg >> 2;
    int r = seg & 3;
    size_t o = (size_t)node * KTOT + r * 128 + lane * 4;
    *reinterpret_cast<uint2*>(&g_ah[o]) = *reinterpret_cast<uint2*>(h);
}

// ---------------- HMMA GEMM + fused relu/residual/LayerNorm, occupancy-2 ----------------
// smem: [0:512) bias, [512:1024) gamma, [1024:1536) beta
//       A tiles (double buffered): 2048 + buf*16384
//       B tile (single buffered):  2048 + 32768
//       LN row partials (post-mainloop, reuse tile area): 2048 sSum[128][2], 3072 sSq[128][2]
#define SMEM_DYN (2048 + 2 * 16384 + 16384)   // 51200 -> 2 CTAs/SM

__global__ void __launch_bounds__(256, 2) k_gemm(int layer, const float* __restrict__ bias,
                                                 const float* __restrict__ gamma,
                                                 const float* __restrict__ beta,
                                                 const float* __restrict__ xin,
                                                 float* __restrict__ xout,
                                                 int write_next) {
    extern __shared__ char smem[];
    float* sBias  = (float*)smem;
    float* sGamma = (float*)(smem + 512);
    float* sBeta  = (float*)(smem + 1024);
    uint32_t smem_u = smem_to_u32(smem);
    int tid = threadIdx.x;
    int wid = tid >> 5;
    int lane = tid & 31;
    int brow = blockIdx.x * 128;

    if (tid < 32) {
        *reinterpret_cast<float4*>(&sBias[tid * 4]) =
            *reinterpret_cast<const float4*>(bias + tid * 4);
        *reinterpret_cast<float4*>(&sGamma[tid * 4]) =
            *reinterpret_cast<const float4*>(gamma + tid * 4);
        *reinterpret_cast<float4*>(&sBeta[tid * 4]) =
            *reinterpret_cast<const float4*>(beta + tid * 4);
    }

    const __half* bh = g_bh + (size_t)layer * D * KTOT;

    // warp tile: 32 (m) x 64 (n)
    int wm = wid & 3;            // m0 = wm*32
    int wn = wid >> 2;           // n0 = wn*64
    int lrow = lane & 15;
    int kh16 = (lane >> 4) * 16;

    const uint32_t bBase = smem_u + 2048 + 32768;

    float acc[2][8][4];
#pragma unroll
    for (int t = 0; t < 2; t++)
#pragma unroll
        for (int q = 0; q < 8; q++)
#pragma unroll
            for (int j = 0; j < 4; j++) acc[t][q][j] = 0.f;

    auto load_A = [&](int c, int buf) {
        uint32_t base = smem_u + 2048 + buf * 16384;
        int kcol = c * 64;
#pragma unroll
        for (int it = 0; it < 4; it++) {
            int u = tid + it * 256;          // 0..1023
            int row = u >> 3;                // 0..127
            int c16 = u & 7;
            uint32_t off = row * 128 + c16 * 16;
            uint32_t sw = off ^ ((off >> 3) & 0x70);
            CP16(base + sw, &g_ah[(size_t)(brow + row) * KTOT + kcol + c16 * 8]);
        }
        asm volatile("cp.async.commit_group;" ::: "memory");
    };
    auto load_B = [&](int c) {
        int kcol = c * 64;
#pragma unroll
        for (int it = 0; it < 4; it++) {
            int u = tid + it * 256;          // 0..1023 -> full 128 rows
            int row = u >> 3;
            int c16 = u & 7;
            uint32_t off = row * 128 + c16 * 16;
            uint32_t sw = off ^ ((off >> 3) & 0x70);
            CP16(bBase + sw, &bh[(size_t)row * KTOT + kcol + c16 * 8]);
        }
        asm volatile("cp.async.commit_group;" ::: "memory");
    };

    load_A(0, 0);
    load_B(0);

    for (int c = 0; c < NCHUNK; c++) {
        asm volatile("cp.async.wait_group 0;" ::: "memory");
        __syncthreads();
        if (c + 1 < NCHUNK) load_A(c + 1, (c + 1) & 1);   // A buffer (c+1)&1 is free

        uint32_t base = smem_u + 2048 + (c & 1) * 16384;
#pragma unroll
        for (int ks = 0; ks < 4; ks++) {
            int kb = ks * 32 + kh16;
            uint32_t ah[2][4], bhf[4][4];
#pragma unroll
            for (int t = 0; t < 2; t++) {
                int row = wm * 32 + t * 16 + lrow;
                uint32_t off = row * 128 + kb;
                ldsm_x4(ah[t], base + (off ^ ((off >> 3) & 0x70)));
            }
#pragma unroll
            for (int p = 0; p < 4; p++) {
                int row = wn * 64 + p * 16 + lrow;
                uint32_t off = row * 128 + kb;
                ldsm_x4(bhf[p], bBase + (off ^ ((off >> 3) & 0x70)));
            }
#pragma unroll
            for (int t = 0; t < 2; t++)
#pragma unroll
                for (int p = 0; p < 4; p++) {
                    mma16816(acc[t][2 * p + 0], ah[t], bhf[p][0], bhf[p][2]);
                    mma16816(acc[t][2 * p + 1], ah[t], bhf[p][1], bhf[p][3]);
                }
        }
        __syncthreads();                         // all warps done with B(c)
        if (c + 1 < NCHUNK) load_B(c + 1);       // refill single B buffer
    }
    // after final __syncthreads above, tile smem is dead -> reuse for LN partials

    float* sSum = (float*)(smem + 2048);   // [128][2]
    float* sSq  = (float*)(smem + 3072);   // [128][2]

    // ---- step 1: v = relu(acc + bias) + xin ; accumulate per-row partials ----
    float psum[2][2], psq[2][2];
#pragma unroll
    for (int t = 0; t < 2; t++) {
        int r0 = brow + wm * 32 + t * 16 + (lane >> 2);
        int r1 = r0 + 8;
        float s0 = 0.f, s1 = 0.f, q0 = 0.f, q1 = 0.f;
#pragma unroll
        for (int q = 0; q < 8; q++) {
            int col = wn * 64 + (q >> 1) * 16 + (q & 1) * 8 + 2 * (lane & 3);
            float bx = sBias[col], by = sBias[col + 1];
            float2 x0 = (r0 < N_NODES)
                ? *reinterpret_cast<const float2*>(xin + (size_t)r0 * D + col)
                : make_float2(0.f, 0.f);
            float2 x1 = (r1 < N_NODES)
                ? *reinterpret_cast<const float2*>(xin + (size_t)r1 * D + col)
                : make_float2(0.f, 0.f);
            float v0 = fmaxf(acc[t][q][0] + bx, 0.f) + x0.x;
            float v1 = fmaxf(acc[t][q][1] + by, 0.f) + x0.y;
            float v2 = fmaxf(acc[t][q][2] + bx, 0.f) + x1.x;
            float v3 = fmaxf(acc[t][q][3] + by, 0.f) + x1.y;
            acc[t][q][0] = v0; acc[t][q][1] = v1;
            acc[t][q][2] = v2; acc[t][q][3] = v3;
            s0 += v0 + v1;  q0 += v0 * v0 + v1 * v1;
            s1 += v2 + v3;  q1 += v2 * v2 + v3 * v3;
        }
        psum[t][0] = s0; psum[t][1] = s1;
        psq[t][0] = q0;  psq[t][1] = q1;
    }
    // quad reduce (4 threads share each row)
#pragma unroll
    for (int t = 0; t < 2; t++)
#pragma unroll
        for (int h = 0; h < 2; h++) {
            psum[t][h] += __shfl_xor_sync(0xFFFFFFFFu, psum[t][h], 1);
            psum[t][h] += __shfl_xor_sync(0xFFFFFFFFu, psum[t][h], 2);
            psq[t][h]  += __shfl_xor_sync(0xFFFFFFFFu, psq[t][h], 1);
            psq[t][h]  += __shfl_xor_sync(0xFFFFFFFFu, psq[t][h], 2);
        }
    if ((lane & 3) == 0) {
#pragma unroll
        for (int t = 0; t < 2; t++) {
            int m0 = wm * 32 + t * 16 + (lane >> 2);
            sSum[m0 * 2 + wn] = psum[t][0];
            sSum[(m0 + 8) * 2 + wn] = psum[t][1];
            sSq[m0 * 2 + wn] = psq[t][0];
            sSq[(m0 + 8) * 2 + wn] = psq[t][1];
        }
    }
    __syncthreads();

    // ---- step 2: LN + write xout (+ fp16 self-cols for next layer) ----
#pragma unroll
    for (int t = 0; t < 2; t++) {
        int m0 = wm * 32 + t * 16 + (lane >> 2);
#pragma unroll
        for (int h = 0; h < 2; h++) {
            int m = m0 + h * 8;
            int row = brow + m;
            if (row >= N_NODES) continue;
            float s = sSum[m * 2 + 0] + sSum[m * 2 + 1];
            float sq = sSq[m * 2 + 0] + sSq[m * 2 + 1];
            float mean = s * (1.0f / 128.0f);
            float var = sq * (1.0f / 128.0f) - mean * mean;
            float rs = rsqrtf(var + 1e-5f);
#pragma unroll
            for (int q = 0; q < 8; q++) {
                int col = wn * 64 + (q >> 1) * 16 + (q & 1) * 8 + 2 * (lane & 3);
                float o0 = (acc[t][q][2 * h + 0] - mean) * rs * sGamma[col] + sBeta[col];
                float o1 = (acc[t][q][2 * h + 1] - mean) * rs * sGamma[col + 1] + sBeta[col + 1];
                *reinterpret_cast<float2*>(xout + (size_t)row * D + col) =
                    make_float2(o0, o1);
                if (write_next) {
                    __half2 hp = __floats2half2_rn(o0, o1);
                    *reinterpret_cast<__half2*>(
                        &g_ah[(size_t)row * KTOT + 512 + col]) = hp;
                }
            }
        }
    }
}

// ---------------- host launcher ----------------
extern "C" void kernel_launch(void* const* d_in, const int* in_sizes, int n_in,
                              void* d_out, int out_size) {
    const float* x     = (const float*)d_in[0];
    const int*   ei    = (const int*)d_in[1];
    const int*   et    = (const int*)d_in[2];
    const float* W     = (const float*)d_in[3];
    const float* root  = (const float*)d_in[4];
    const float* bias  = (const float*)d_in[5];
    const float* gamma = (const float*)d_in[6];
    const float* beta  = (const float*)d_in[7];
    float* out = (float*)d_out;

    const int* src = ei;
    const int* dst = ei + N_EDGES;

    float *px1 = nullptr, *px2 = nullptr;
    cudaGetSymbolAddress((void**)&px1, g_x1);
    cudaGetSymbolAddress((void**)&px2, g_x2);

    cudaFuncSetAttribute(k_gemm, cudaFuncAttributeMaxDynamicSharedMemorySize, SMEM_DYN);

    // CSR build (edge structure is layer-invariant)
    k_zero_cnt<<<(NSEG + 255) / 256, 256>>>();
    k_hist<<<(N_EDGES + 255) / 256, 256>>>(dst, et);
    int nb = (NSEG + 1023) / 1024;
    k_scan1<<<nb, 1024>>>();
    k_scan23<<<nb, 1024>>>(nb);
    k_scatter<<<(N_EDGES + 255) / 256, 256>>>(src, dst, et);

    // weight transpose + fp16
    k_bprep<<<(NLAYER * D * KTOT + 255) / 256, 256>>>(W, root);
    // self-cols for layer 0 (must precede first k_agg — it gathers from them)
    k_convx<<<(N_NODES + 7) / 8, 256>>>(x);

    const float* xin = x;
    for (int l = 0; l < NLAYER; l++) {
        k_agg<<<(NSEG + 7) / 8, 256>>>();
        float* xout = (l == NLAYER - 1) ? out : ((l == 0) ? px1 : px2);
        k_gemm<<<NTILES, 256, SMEM_DYN>>>(l, bias + (size_t)l * D,
                                          gamma + (size_t)l * D,
                                          beta + (size_t)l * D,
                                          xin, xout,
                                          l < NLAYER - 1 ? 1 : 0);
        xin = xout;
    }
}